// round 13
// baseline (speedup 1.0000x reference)
#include <cuda_runtime.h>
#include <cuda_fp16.h>
#include <cstdint>

#define HN 16
#define DH 64
#define EM 1024
#define SQ 1024
#define BA 8
#define BH (BA*HN)
#define NTOK (BA*SQ)

// Scratch (device globals; allocation-free per harness rules)
__device__ __half g_hid_h[NTOK*EM];
__device__ __half g_wt[3*EM*EM];      // [3072 n][1024 k] (W^T, fp16)
__device__ __half g_wot[EM*EM];       // [1024 n][1024 k]
__device__ __half g_qh[BH*SQ*DH];
__device__ __half g_kh[BH*SQ*DH];
__device__ __half g_vh[BH*SQ*DH];
__device__ __half g_ctx_h[NTOK*EM];
__device__ __half g_dist_h[2047*DH];  // pre-scaled by C2F
__device__ float  g_biasqkv[3*EM];
__device__ float  g_h[NTOK*EM];

// ---------------------------------------------------------------------------
// PTX helpers (all non-'a' features: sm_80-class, compile at sm_103)
// ---------------------------------------------------------------------------
__device__ __forceinline__ uint32_t s2u(const void* p){
    uint32_t a; asm("{ .reg .u64 t; cvta.to.shared.u64 t, %1; cvt.u32.u64 %0, t; }" : "=r"(a) : "l"(p)); return a;
}
__device__ __forceinline__ void ldsm4(uint32_t& r0, uint32_t& r1, uint32_t& r2, uint32_t& r3, uint32_t addr){
    asm volatile("ldmatrix.sync.aligned.m8n8.x4.shared.b16 {%0,%1,%2,%3}, [%4];"
        : "=r"(r0), "=r"(r1), "=r"(r2), "=r"(r3) : "r"(addr));
}
__device__ __forceinline__ void ldsm4t(uint32_t& r0, uint32_t& r1, uint32_t& r2, uint32_t& r3, uint32_t addr){
    asm volatile("ldmatrix.sync.aligned.m8n8.x4.trans.shared.b16 {%0,%1,%2,%3}, [%4];"
        : "=r"(r0), "=r"(r1), "=r"(r2), "=r"(r3) : "r"(addr));
}
__device__ __forceinline__ void mmaf16(float c[4], const uint32_t a[4], uint32_t b0, uint32_t b1){
    asm volatile("mma.sync.aligned.m16n8k16.row.col.f32.f16.f16.f32 "
        "{%0,%1,%2,%3}, {%4,%5,%6,%7}, {%8,%9}, {%0,%1,%2,%3};"
        : "+f"(c[0]), "+f"(c[1]), "+f"(c[2]), "+f"(c[3])
        : "r"(a[0]), "r"(a[1]), "r"(a[2]), "r"(a[3]), "r"(b0), "r"(b1));
}
// fp16-accumulator variant: c = 2 regs of packed half2 (rows g / g+8)
__device__ __forceinline__ void mmah16(uint32_t c[2], const uint32_t a[4], uint32_t b0, uint32_t b1){
    asm volatile("mma.sync.aligned.m16n8k16.row.col.f16.f16.f16.f16 "
        "{%0,%1}, {%2,%3,%4,%5}, {%6,%7}, {%0,%1};"
        : "+r"(c[0]), "+r"(c[1])
        : "r"(a[0]), "r"(a[1]), "r"(a[2]), "r"(a[3]), "r"(b0), "r"(b1));
}
__device__ __forceinline__ void cp16(uint32_t dst, const void* src){
    asm volatile("cp.async.ca.shared.global [%0], [%1], 16;" :: "r"(dst), "l"(src));
}
__device__ __forceinline__ void cp16cg(uint32_t dst, const void* src){
    asm volatile("cp.async.cg.shared.global [%0], [%1], 16;" :: "r"(dst), "l"(src));
}
__device__ __forceinline__ void cp_commit(){ asm volatile("cp.async.commit_group;" ::: "memory"); }
template<int N> __device__ __forceinline__ void cp_wait(){
    asm volatile("cp.async.wait_group %0;" :: "n"(N) : "memory");
}
__device__ __forceinline__ float ex2(float x){
    float y; asm("ex2.approx.f32 %0, %1;" : "=f"(y) : "f"(x)); return y;
}
__device__ __forceinline__ void barp(int id){
    asm volatile("bar.sync %0, 64;" :: "r"(id) : "memory");
}

#define C2F 0.18033688f         // 0.125 * log2(e)

// ---------------------------------------------------------------------------
// Pack kernels
// ---------------------------------------------------------------------------
__global__ __launch_bounds__(256) void pack_h_kernel(const float* __restrict__ src,
                                                     __half* __restrict__ dst, int n4)
{
    int i = blockIdx.x*256 + threadIdx.x;
    if (i < n4){
        float4 v = ((const float4*)src)[i];
        __half2* d = (__half2*)dst + i*2;
        d[0] = __floats2half2_rn(v.x, v.y);
        d[1] = __floats2half2_rn(v.z, v.w);
    }
}

// z=0..3: weight transposes Wq,Wk,Wv,Wo.  z=4: dist fp16 pack (pre-scaled by C2F) + bias copy.
__global__ __launch_bounds__(256) void pack_wt_all(const float* __restrict__ Wq,
    const float* __restrict__ Wk, const float* __restrict__ Wv,
    const float* __restrict__ Wo, const float* __restrict__ dist,
    const float* __restrict__ bq, const float* __restrict__ bk,
    const float* __restrict__ bv)
{
    int z = blockIdx.z;
    if (z == 4){
        int bid = blockIdx.y*32 + blockIdx.x;
        int i = bid*256 + threadIdx.x;
        const int ND4 = 2047*DH/4;           // 32752 float4 of dist
        if (i < ND4){
            float4 v = ((const float4*)dist)[i];
            __half2* d = (__half2*)g_dist_h + i*2;
            d[0] = __floats2half2_rn(v.x*C2F, v.y*C2F);
            d[1] = __floats2half2_rn(v.z*C2F, v.w*C2F);
        } else {
            int j = i - ND4;
            if (j < 3*EM){
                int b = j >> 10, e = j & 1023;
                const float* s = (b==0) ? bq : (b==1 ? bk : bv);
                g_biasqkv[j] = s[e];
            }
        }
        return;
    }
    __shared__ float t[32][33];
    const float* W = (z==0)?Wq:(z==1)?Wk:(z==2)?Wv:Wo;
    __half* Wt = (z<3) ? (g_wt + (size_t)z*EM*EM) : g_wot;
    int bn = blockIdx.x*32, bk2 = blockIdx.y*32;
    int tx = threadIdx.x & 31, ty = threadIdx.x >> 5;
    #pragma unroll
    for (int i=0;i<32;i+=8)
        t[ty+i][tx] = W[(size_t)(bk2+ty+i)*EM + bn+tx];
    __syncthreads();
    #pragma unroll
    for (int i=0;i<32;i+=8)
        Wt[(size_t)(bn+ty+i)*EM + bk2+tx] = __float2half_rn(t[tx][ty+i]);
}

// ---------------------------------------------------------------------------
// fp16 GEMM: C[128 x 128] tile, K=1024, 4-stage cp.async, ldmatrix + mma16816.
// ---------------------------------------------------------------------------
#define GSTG (128*40*2)       // 10240 B per A or B tile
#define GSMEM (4*2*GSTG)      // 81920

__global__ __launch_bounds__(256,2) void gemm_h(const __half* __restrict__ A,
    const __half* __restrict__ Bt, const float* __restrict__ bias,
    const float* __restrict__ resid, int mode)
{
    extern __shared__ char sm[];
    uint32_t sb = s2u(sm);
    int tid = threadIdx.x, w = tid>>5, lane = tid&31;
    int g = lane>>2, tig = lane&3;
    int rows0 = (w>>2)*64, cols0 = (w&3)*32;
    int m0 = blockIdx.x*128, n0 = blockIdx.y*128;

    float c[4][4][4];
    #pragma unroll
    for (int i=0;i<4;i++)
        #pragma unroll
        for (int j=0;j<4;j++){ c[i][j][0]=0.f; c[i][j][1]=0.f; c[i][j][2]=0.f; c[i][j][3]=0.f; }

    auto load_st = [&](int st, int kc){
        uint32_t base = sb + st*2*GSTG;
        const __half* gA = A + (size_t)m0*EM + kc*32;
        const __half* gB = Bt + (size_t)n0*EM + kc*32;
        #pragma unroll
        for (int i=0;i<2;i++){
            int cix = tid + 256*i;
            int row = cix>>2, part = cix&3;
            cp16(base + row*80 + part*16, gA + (size_t)row*EM + part*8);
        }
        #pragma unroll
        for (int i=0;i<2;i++){
            int cix = tid + 256*i;
            int row = cix>>2, part = cix&3;
            cp16(base + GSTG + row*80 + part*16, gB + (size_t)row*EM + part*8);
        }
    };

    #pragma unroll
    for (int s=0;s<3;s++){ load_st(s, s); cp_commit(); }

    int a_r = lane & 15;
    int a_k = (lane>>4)<<3;
    int b_n = (lane&7) + ((lane>=16)?8:0);
    int b_k = (lane&8)?8:0;

    for (int kc=0; kc<32; kc++){
        if (kc+3 < 32) load_st((kc+3)&3, kc+3);
        cp_commit();
        cp_wait<3>();
        __syncthreads();
        uint32_t Ab = sb + (kc&3)*2*GSTG;
        uint32_t Bb = Ab + GSTG;
        #pragma unroll
        for (int ks=0; ks<2; ks++){
            uint32_t a[4][4];
            #pragma unroll
            for (int mi=0;mi<4;mi++)
                ldsm4(a[mi][0],a[mi][1],a[mi][2],a[mi][3],
                      Ab + (rows0+16*mi+a_r)*80 + (ks*16 + a_k)*2);
            #pragma unroll
            for (int ni2=0;ni2<2;ni2++){
                uint32_t b0,b1,b2,b3;
                ldsm4(b0,b1,b2,b3, Bb + (cols0+16*ni2+b_n)*80 + (ks*16 + b_k)*2);
                #pragma unroll
                for (int mi=0;mi<4;mi++){
                    mmaf16(c[mi][2*ni2],   a[mi], b0, b1);
                    mmaf16(c[mi][2*ni2+1], a[mi], b2, b3);
                }
            }
        }
        __syncthreads();
    }

    #pragma unroll
    for (int mi=0; mi<4; mi++){
        int rowA = rows0 + 16*mi + g;
        int t1 = m0 + rowA, t2 = t1 + 8;
        #pragma unroll
        for (int ni=0; ni<4; ni++){
            int col = cols0 + 8*ni + 2*tig;
            int nglob = n0 + col;
            float bv0 = bias[nglob], bv1 = bias[nglob+1];
            if (mode == 0){
                int mat = nglob>>10, e = nglob&1023, h = e>>6, d = e&63;
                __half* outp = (mat==0) ? g_qh : (mat==1 ? g_kh : g_vh);
                int bb1 = t1>>10, s1 = t1&1023;
                int bb2 = t2>>10, s2 = t2&1023;
                *(__half2*)&outp[(((size_t)(bb1*HN+h))*SQ + s1)*DH + d] =
                    __floats2half2_rn(c[mi][ni][0]+bv0, c[mi][ni][1]+bv1);
                *(__half2*)&outp[(((size_t)(bb2*HN+h))*SQ + s2)*DH + d] =
                    __floats2half2_rn(c[mi][ni][2]+bv0, c[mi][ni][3]+bv1);
            } else {
                const float* r1 = &resid[(size_t)t1*EM + nglob];
                const float* r2 = &resid[(size_t)t2*EM + nglob];
                float2 v1; v1.x = c[mi][ni][0]+bv0+r1[0]; v1.y = c[mi][ni][1]+bv1+r1[1];
                float2 v2; v2.x = c[mi][ni][2]+bv0+r2[0]; v2.y = c[mi][ni][3]+bv1+r2[1];
                *(float2*)&g_h[(size_t)t1*EM + nglob] = v1;
                *(float2*)&g_h[(size_t)t2*EM + nglob] = v2;
            }
        }
    }
}

// ---------------------------------------------------------------------------
// Flash attention, 512 threads, warp pairs, max-free softmax, double-buffered
// K/V, compact QD/KD, D ring. Rel band uses fp16-ACCUMULATOR mma (outputs are
// fp16 in smem anyway); D pre-scaled by C2F so rel stores are raw reg copies.
// ---------------------------------------------------------------------------
#define LDT 144                 // bytes per 64-half row (128 data + 16 pad)
#define LQD 368                 // bytes per compact QD/KD row (184 halves)
#define OQ  0
#define OKA 18432
#define OKB 36864
#define OVA 55296
#define OVB 73728
#define OD  92160               // 256-row ring x 144B
#define OQD 129024              // 128 x LQD   (u = t - 16r)
#define OKD 176128              // 128 x LQD   (v = t - 112 + 16r)
#define OSX 223232
#define ATTN_SMEM 225280

__global__ __launch_bounds__(512,1) void attn_h()
{
    extern __shared__ char sm[];
    uint32_t sb = s2u(sm);

    int bh = blockIdx.x;
    int l0 = blockIdx.y*128;
    int tid = threadIdx.x;
    int w = tid>>5, lane = tid&31, g = lane>>2, tig = lane&3;
    int r = w>>1, wc = w&1;

    int a_r = lane & 15;
    int a_k = (lane>>4)<<3;
    int b_n = (lane&7) + ((lane>=16)?8:0);
    int b_k = (lane&8)?8:0;
    int t_k = (lane&7) + ((lane&8)?8:0);
    int t_n = (lane>=16)?8:0;
    int i0 = 16*r + g;

    // zero logical dist row 255 for rt=0
    if (tid < 9) *(uint4*)(sm + OD + 255*LDT + tid*16) = make_uint4(0,0,0,0);

    // prologue: group A = Q + K0->KA + V0->VA ; group B = D0 (255 rows)
    {
        const __half* qg = g_qh + ((size_t)bh*SQ + l0)*DH;
        const __half* kg = g_kh + ((size_t)bh*SQ)*DH;
        const __half* vg = g_vh + ((size_t)bh*SQ)*DH;
        #pragma unroll
        for (int i=0;i<2;i++){
            int cix = tid + 512*i;
            int row = cix>>3, part = cix&7;
            cp16cg(sb + OQ  + row*LDT + part*16, qg + (size_t)row*DH + part*8);
            cp16cg(sb + OKA + row*LDT + part*16, kg + (size_t)row*DH + part*8);
            cp16cg(sb + OVA + row*LDT + part*16, vg + (size_t)row*DH + part*8);
        }
        cp_commit();
        const __half* dg = g_dist_h + (size_t)(l0 + 896)*DH;
        #pragma unroll
        for (int i=0;i<4;i++){
            int cix = tid + 512*i;
            if (cix < 255*8){
                int row = cix>>3, part = cix&7;
                cp16cg(sb + OD + row*LDT + part*16, dg + (size_t)row*DH + part*8);
            }
        }
        cp_commit();
    }

    float o[8][4];
    #pragma unroll
    for (int i=0;i<8;i++){ o[i][0]=0.f; o[i][1]=0.f; o[i][2]=0.f; o[i][3]=0.f; }
    float lrow0 = 0.f, lrow1 = 0.f;

    uint32_t qa[4][4];
    float* SX = (float*)(sm + OSX);

    for (int rt=0; rt<8; rt++){
        cp_wait<0>();
        __syncthreads();               // K, V (top group) + D (mid group) for rt ready

        uint32_t kb = sb + ((rt&1) ? OKB : OKA);
        uint32_t vb = sb + ((rt&1) ? OVB : OVA);

        if (rt == 0){
            #pragma unroll
            for (int ks=0;ks<4;ks++)
                ldsm4(qa[ks][0],qa[ks][1],qa[ks][2],qa[ks][3],
                      sb + OQ + (16*r+a_r)*LDT + (ks*16 + a_k)*2);
        }
        if (rt < 7){                   // prefetch K,V for rt+1 into the other buffers
            uint32_t kn = sb + ((rt&1) ? OKA : OKB);
            uint32_t vn = sb + ((rt&1) ? OVA : OVB);
            const __half* kg = g_kh + ((size_t)bh*SQ + (rt+1)*128)*DH;
            const __half* vg = g_vh + ((size_t)bh*SQ + (rt+1)*128)*DH;
            #pragma unroll
            for (int i=0;i<2;i++){
                int cix = tid + 512*i;
                int row = cix>>3, part = cix&7;
                cp16cg(kn + row*LDT + part*16, kg + (size_t)row*DH + part*8);
                cp16cg(vn + row*LDT + part*16, vg + (size_t)row*DH + part*8);
            }
            cp_commit();
        }

        int rowoff = (rt & 1) << 7;    // D ring offset

        // ---- QD tiles (pair covers [r..r+8]); fp16-accum mma, raw stores ----
        {
            int T0 = wc ? r : (r+5);
            int nT = wc ? 5 : 4;
            for (int ti=0; ti<nT; ti++){
                int t0r = (T0+ti)<<4;
                int u0 = t0r - 16*r;
                uint32_t dbase = sb + OD + (((t0r + b_n) + rowoff) & 255)*LDT;
                uint32_t qd[2][2];
                qd[0][0]=0u; qd[0][1]=0u; qd[1][0]=0u; qd[1][1]=0u;
                #pragma unroll
                for (int ks=0;ks<4;ks++){
                    uint32_t b0,b1,b2,b3;
                    ldsm4(b0,b1,b2,b3, dbase + (ks*16 + b_k)*2);
                    mmah16(qd[0], qa[ks], b0, b1);
                    mmah16(qd[1], qa[ks], b2, b3);
                }
                #pragma unroll
                for (int f=0;f<2;f++){
                    int u = u0 + 8*f + 2*tig;
                    *(uint32_t*)(sm + OQD + (size_t)i0*LQD + u*2)     = qd[f][0];
                    *(uint32_t*)(sm + OQD + (size_t)(i0+8)*LQD + u*2) = qd[f][1];
                }
            }
        }

        // ---- ka fragments (feed only KD) ----
        uint32_t ka[4][4];
        #pragma unroll
        for (int ks=0;ks<4;ks++)
            ldsm4(ka[ks][0],ka[ks][1],ka[ks][2],ka[ks][3],
                  kb + (16*r+a_r)*LDT + (ks*16 + a_k)*2);

        // ---- KD tiles (pair covers [7-r..15-r]); fp16-accum mma, raw stores ----
        {
            int T0 = wc ? (7-r) : (12-r);
            int nT = wc ? 5 : 4;
            for (int ti=0; ti<nT; ti++){
                int t0r = (T0+ti)<<4;
                int v0 = t0r - 112 + 16*r;
                uint32_t dbase = sb + OD + (((t0r + b_n) + rowoff) & 255)*LDT;
                uint32_t kd[2][2];
                kd[0][0]=0u; kd[0][1]=0u; kd[1][0]=0u; kd[1][1]=0u;
                #pragma unroll
                for (int ks=0;ks<4;ks++){
                    uint32_t b0,b1,b2,b3;
                    ldsm4(b0,b1,b2,b3, dbase + (ks*16 + b_k)*2);
                    mmah16(kd[0], ka[ks], b0, b1);
                    mmah16(kd[1], ka[ks], b2, b3);
                }
                #pragma unroll
                for (int f=0;f<2;f++){
                    int v = v0 + 8*f + 2*tig;
                    *(uint32_t*)(sm + OKD + (size_t)i0*LQD + v*2)     = kd[f][0];
                    *(uint32_t*)(sm + OKD + (size_t)(i0+8)*LQD + v*2) = kd[f][1];
                }
            }
        }

        // ---- S = Q @ K^T (warp tile 16 x 64: cols [64wc, 64wc+64)) ----
        float cs[8][4];
        #pragma unroll
        for (int f=0;f<8;f++){ cs[f][0]=0.f; cs[f][1]=0.f; cs[f][2]=0.f; cs[f][3]=0.f; }
        #pragma unroll
        for (int ks=0;ks<4;ks++){
            #pragma unroll
            for (int ntl=0;ntl<4;ntl++){
                uint32_t b0,b1,b2,b3;
                ldsm4(b0,b1,b2,b3, kb + (16*(4*wc+ntl)+b_n)*LDT + (ks*16 + b_k)*2);
                mmaf16(cs[2*ntl],   qa[ks], b0, b1);
                mmaf16(cs[2*ntl+1], qa[ks], b2, b3);
            }
        }

        __syncthreads();               // QD/KD STS visible; D ring reads done

        if (rt < 7){                   // prefetch D(rt+1) into free ring half
            int poff = ((rt+1) & 1) << 7;
            const __half* dg = g_dist_h + (size_t)(l0 - (rt+1)*128 + 896)*DH;
            #pragma unroll
            for (int i=0;i<2;i++){
                int cix = tid + 512*i;
                int row = cix>>3, part = cix&7;
                cp16cg(sb + OD + (row + poff)*LDT + part*16, dg + (size_t)row*DH + part*8);
            }
            cp_commit();
        }

        // ---- max-free softmax: gather from compact layouts, exp2, pack ----
        {
            const char* QDb = sm + OQD;
            const char* KDb = sm + OKD;
            uint32_t p[8][2];
            #pragma unroll
            for (int f=0;f<8;f++){
                int j = 64*wc + 8*f + 2*tig;
                int uq = g + 127 - j;              // QD col for (i0, j)
                int jl = (8*f + 2*tig) & 15;
                int v00 = i0 + 15 - jl;            // KD col for (row j, i0)
                float b00 = __half2float(*(const __half*)(QDb + (size_t)i0*LQD + uq*2))
                          + __half2float(*(const __half*)(KDb + (size_t)j*LQD + v00*2));
                float b01 = __half2float(*(const __half*)(QDb + (size_t)i0*LQD + (uq-1)*2))
                          + __half2float(*(const __half*)(KDb + (size_t)(j+1)*LQD + (v00-1)*2));
                float b10 = __half2float(*(const __half*)(QDb + (size_t)(i0+8)*LQD + (uq+8)*2))
                          + __half2float(*(const __half*)(KDb + (size_t)j*LQD + (v00+8)*2));
                float b11 = __half2float(*(const __half*)(QDb + (size_t)(i0+8)*LQD + (uq+7)*2))
                          + __half2float(*(const __half*)(KDb + (size_t)(j+1)*LQD + (v00+7)*2));
                float p00 = ex2(fmaf(cs[f][0], C2F, b00));
                float p01 = ex2(fmaf(cs[f][1], C2F, b01));
                float p10 = ex2(fmaf(cs[f][2], C2F, b10));
                float p11 = ex2(fmaf(cs[f][3], C2F, b11));
                lrow0 += p00 + p01; lrow1 += p10 + p11;
                __half2 hA = __floats2half2_rn(p00, p01); p[f][0] = *(uint32_t*)&hA;
                __half2 hB = __floats2half2_rn(p10, p11); p[f][1] = *(uint32_t*)&hB;
            }

            // ---- O += P @ V over this warp's 64-key slice ----
            #pragma unroll
            for (int kl=0;kl<4;kl++){
                int kk = 4*wc + kl;
                uint32_t a[4] = { p[2*kl][0], p[2*kl][1], p[2*kl+1][0], p[2*kl+1][1] };
                #pragma unroll
                for (int ni2=0;ni2<4;ni2++){
                    uint32_t v0,v1,v2,v3;
                    ldsm4t(v0,v1,v2,v3, vb + (16*kk + t_k)*LDT + (16*ni2 + t_n)*2);
                    mmaf16(o[2*ni2],   a, v0, v1);
                    mmaf16(o[2*ni2+1], a, v2, v3);
                }
            }
        }
        // no end barrier: next iter's top barrier protects all buffers
    }

    // ---- epilogue: reduce l, pair-sum partial O (QD region reused), write ctx ----
    lrow0 += __shfl_xor_sync(0xffffffffu, lrow0, 1);
    lrow0 += __shfl_xor_sync(0xffffffffu, lrow0, 2);
    lrow1 += __shfl_xor_sync(0xffffffffu, lrow1, 1);
    lrow1 += __shfl_xor_sync(0xffffffffu, lrow1, 2);
    SX[i0*2 + wc]     = lrow0;
    SX[(i0+8)*2 + wc] = lrow1;
    barp(1 + r);                       // partner's last gather reads done

    float* OS = (float*)(sm + OQD);    // [128][66] floats fits in QD region
    if (wc == 0){
        #pragma unroll
        for (int ni=0; ni<8; ni++){
            int d = 8*ni + 2*tig;
            OS[i0*66 + d]       = o[ni][0];
            OS[i0*66 + d + 1]   = o[ni][1];
            OS[(i0+8)*66 + d]   = o[ni][2];
            OS[(i0+8)*66 + d+1] = o[ni][3];
        }
    }
    barp(1 + r);
    if (wc == 1){
        float lt0 = lrow0 + SX[i0*2 + 0];
        float lt1 = lrow1 + SX[(i0+8)*2 + 0];
        float inv0 = 1.f / lt0;
        float inv1 = 1.f / lt1;
        int bb = bh>>4, hh = bh&15;
        int s1r = l0 + i0;
        __half* base1 = g_ctx_h + ((size_t)(bb*SQ + s1r  ))*EM + hh*DH;
        __half* base2 = g_ctx_h + ((size_t)(bb*SQ + s1r+8))*EM + hh*DH;
        #pragma unroll
        for (int ni=0; ni<8; ni++){
            int d = 8*ni + 2*tig;
            float v0 = (o[ni][0] + OS[i0*66 + d])       * inv0;
            float v1 = (o[ni][1] + OS[i0*66 + d + 1])   * inv0;
            float v2 = (o[ni][2] + OS[(i0+8)*66 + d])   * inv1;
            float v3 = (o[ni][3] + OS[(i0+8)*66 + d+1]) * inv1;
            *(__half2*)&base1[d] = __floats2half2_rn(v0, v1);
            *(__half2*)&base2[d] = __floats2half2_rn(v2, v3);
        }
    }
}

// ---------------------------------------------------------------------------
// LayerNorm: 512 threads, 2 rows per block
// ---------------------------------------------------------------------------
__global__ __launch_bounds__(512) void ln_kernel(const float* __restrict__ gamma,
    const float* __restrict__ beta, float* __restrict__ out)
{
    int hf = threadIdx.x >> 8;           // 0/1: which row
    int tid = threadIdx.x & 255;
    int row = blockIdx.x*2 + hf;
    int w = tid>>5, lane = tid&31;
    const float4 x4 = ((const float4*)(g_h + (size_t)row*EM))[tid];
    float s = x4.x + x4.y + x4.z + x4.w;
    float q = x4.x*x4.x + x4.y*x4.y + x4.z*x4.z + x4.w*x4.w;
    #pragma unroll
    for (int off=16; off; off>>=1){
        s += __shfl_xor_sync(0xffffffffu, s, off);
        q += __shfl_xor_sync(0xffffffffu, q, off);
    }
    __shared__ float ss[2][8], qs[2][8];
    __shared__ float mean_s[2], rs_s[2];
    if (lane==0){ ss[hf][w]=s; qs[hf][w]=q; }
    __syncthreads();
    if (w==0){
        float s2 = (lane<8) ? ss[hf][lane] : 0.f;
        float q2 = (lane<8) ? qs[hf][lane] : 0.f;
        #pragma unroll
        for (int off=4; off; off>>=1){
            s2 += __shfl_xor_sync(0xffffffffu, s2, off);
            q2 += __shfl_xor_sync(0xffffffffu, q2, off);
        }
        if (lane==0){
            float mean = s2 * (1.f/1024.f);
            float var  = fmaxf(q2 * (1.f/1024.f) - mean*mean, 0.f);
            mean_s[hf] = mean;
            rs_s[hf]   = rsqrtf(var + 1e-12f);
        }
    }
    __syncthreads();
    float mean = mean_s[hf], rs = rs_s[hf];
    float4 gm = ((const float4*)gamma)[tid];
    float4 bt = ((const float4*)beta)[tid];
    float4 y;
    y.x = (x4.x - mean)*rs*gm.x + bt.x;
    y.y = (x4.y - mean)*rs*gm.y + bt.y;
    y.z = (x4.z - mean)*rs*gm.z + bt.z;
    y.w = (x4.w - mean)*rs*gm.w + bt.w;
    ((float4*)(out + (size_t)row*EM))[tid] = y;
}

// ---------------------------------------------------------------------------
extern "C" void kernel_launch(void* const* d_in, const int* in_sizes, int n_in,
                              void* d_out, int out_size)
{
    const float* hidden = (const float*)d_in[0];
    const float* Wq  = (const float*)d_in[1];
    const float* bq  = (const float*)d_in[2];
    const float* Wk  = (const float*)d_in[3];
    const float* bk  = (const float*)d_in[4];
    const float* Wv  = (const float*)d_in[5];
    const float* bv  = (const float*)d_in[6];
    const float* dist= (const float*)d_in[7];
    const float* Wo  = (const float*)d_in[8];
    const float* bo  = (const float*)d_in[9];
    const float* gam = (const float*)d_in[10];
    const float* bet = (const float*)d_in[11];
    float* out = (float*)d_out;

    cudaFuncSetAttribute(attn_h, cudaFuncAttributeMaxDynamicSharedMemorySize, ATTN_SMEM);
    cudaFuncSetAttribute(gemm_h, cudaFuncAttributeMaxDynamicSharedMemorySize, GSMEM);

    __half *hidh, *wt, *wot, *ctxh;
    float *biasq;
    cudaGetSymbolAddress((void**)&hidh,  g_hid_h);
    cudaGetSymbolAddress((void**)&wt,    g_wt);
    cudaGetSymbolAddress((void**)&wot,   g_wot);
    cudaGetSymbolAddress((void**)&ctxh,  g_ctx_h);
    cudaGetSymbolAddress((void**)&biasq, g_biasqkv);

    // launch order puts attn_h at index 3 (the launch ncu captures)
    pack_h_kernel<<<NTOK*EM/4/256, 256>>>(hidden, hidh, NTOK*EM/4);          // 0
    pack_wt_all<<<dim3(32,32,5), 256>>>(Wq, Wk, Wv, Wo, dist, bq, bk, bv);   // 1
    gemm_h<<<dim3(64,24), 256, GSMEM>>>(hidh, wt, biasq, nullptr, 0);        // 2
    attn_h<<<dim3(128,8), 512, ATTN_SMEM>>>();                               // 3 <- ncu
    gemm_h<<<dim3(64,8), 256, GSMEM>>>(ctxh, wot, bo, hidden, 1);            // 4
    ln_kernel<<<NTOK/2, 512>>>(gam, bet, out);                               // 5
}

// round 14
// speedup vs baseline: 1.5329x; 1.5329x over previous
#include <cuda_runtime.h>
#include <cuda_fp16.h>
#include <cstdint>

#define HN 16
#define DH 64
#define EM 1024
#define SQ 1024
#define BA 8
#define BH (BA*HN)
#define NTOK (BA*SQ)

// Scratch (device globals; allocation-free per harness rules)
__device__ __half g_hid_h[NTOK*EM];
__device__ __half g_wt[3*EM*EM];      // [3072 n][1024 k] (W^T, fp16)
__device__ __half g_wot[EM*EM];       // [1024 n][1024 k]
__device__ __half g_qh[BH*SQ*DH];
__device__ __half g_kh[BH*SQ*DH];
__device__ __half g_vh[BH*SQ*DH];
__device__ __half g_ctx_h[NTOK*EM];
__device__ __half g_dist_h[2047*DH];  // pre-scaled by C2F
__device__ float  g_biasqkv[3*EM];
__device__ float  g_h[NTOK*EM];

// ---------------------------------------------------------------------------
// PTX helpers (all non-'a' features: sm_80-class, compile at sm_103)
// ---------------------------------------------------------------------------
__device__ __forceinline__ uint32_t s2u(const void* p){
    uint32_t a; asm("{ .reg .u64 t; cvta.to.shared.u64 t, %1; cvt.u32.u64 %0, t; }" : "=r"(a) : "l"(p)); return a;
}
__device__ __forceinline__ void ldsm4(uint32_t& r0, uint32_t& r1, uint32_t& r2, uint32_t& r3, uint32_t addr){
    asm volatile("ldmatrix.sync.aligned.m8n8.x4.shared.b16 {%0,%1,%2,%3}, [%4];"
        : "=r"(r0), "=r"(r1), "=r"(r2), "=r"(r3) : "r"(addr));
}
__device__ __forceinline__ void ldsm4t(uint32_t& r0, uint32_t& r1, uint32_t& r2, uint32_t& r3, uint32_t addr){
    asm volatile("ldmatrix.sync.aligned.m8n8.x4.trans.shared.b16 {%0,%1,%2,%3}, [%4];"
        : "=r"(r0), "=r"(r1), "=r"(r2), "=r"(r3) : "r"(addr));
}
__device__ __forceinline__ void mmaf16(float c[4], const uint32_t a[4], uint32_t b0, uint32_t b1){
    asm volatile("mma.sync.aligned.m16n8k16.row.col.f32.f16.f16.f32 "
        "{%0,%1,%2,%3}, {%4,%5,%6,%7}, {%8,%9}, {%0,%1,%2,%3};"
        : "+f"(c[0]), "+f"(c[1]), "+f"(c[2]), "+f"(c[3])
        : "r"(a[0]), "r"(a[1]), "r"(a[2]), "r"(a[3]), "r"(b0), "r"(b1));
}
__device__ __forceinline__ void cp16(uint32_t dst, const void* src){
    asm volatile("cp.async.ca.shared.global [%0], [%1], 16;" :: "r"(dst), "l"(src));
}
__device__ __forceinline__ void cp16cg(uint32_t dst, const void* src){
    asm volatile("cp.async.cg.shared.global [%0], [%1], 16;" :: "r"(dst), "l"(src));
}
__device__ __forceinline__ void cp_commit(){ asm volatile("cp.async.commit_group;" ::: "memory"); }
template<int N> __device__ __forceinline__ void cp_wait(){
    asm volatile("cp.async.wait_group %0;" :: "n"(N) : "memory");
}
__device__ __forceinline__ float ex2(float x){
    float y; asm("ex2.approx.f32 %0, %1;" : "=f"(y) : "f"(x)); return y;
}
__device__ __forceinline__ void barp(int id){
    asm volatile("bar.sync %0, 64;" :: "r"(id) : "memory");
}

#define C2F 0.18033688f         // 0.125 * log2(e)

// ---------------------------------------------------------------------------
// Pack kernels
// ---------------------------------------------------------------------------
__global__ __launch_bounds__(256) void pack_h_kernel(const float* __restrict__ src,
                                                     __half* __restrict__ dst, int n4)
{
    int i = blockIdx.x*256 + threadIdx.x;
    if (i < n4){
        float4 v = ((const float4*)src)[i];
        __half2* d = (__half2*)dst + i*2;
        d[0] = __floats2half2_rn(v.x, v.y);
        d[1] = __floats2half2_rn(v.z, v.w);
    }
}

// z=0..3: weight transposes Wq,Wk,Wv,Wo.  z=4: dist fp16 pack (pre-scaled by C2F) + bias copy.
__global__ __launch_bounds__(256) void pack_wt_all(const float* __restrict__ Wq,
    const float* __restrict__ Wk, const float* __restrict__ Wv,
    const float* __restrict__ Wo, const float* __restrict__ dist,
    const float* __restrict__ bq, const float* __restrict__ bk,
    const float* __restrict__ bv)
{
    int z = blockIdx.z;
    if (z == 4){
        int bid = blockIdx.y*32 + blockIdx.x;
        int i = bid*256 + threadIdx.x;
        const int ND4 = 2047*DH/4;           // 32752 float4 of dist
        if (i < ND4){
            float4 v = ((const float4*)dist)[i];
            __half2* d = (__half2*)g_dist_h + i*2;
            d[0] = __floats2half2_rn(v.x*C2F, v.y*C2F);
            d[1] = __floats2half2_rn(v.z*C2F, v.w*C2F);
        } else {
            int j = i - ND4;
            if (j < 3*EM){
                int b = j >> 10, e = j & 1023;
                const float* s = (b==0) ? bq : (b==1 ? bk : bv);
                g_biasqkv[j] = s[e];
            }
        }
        return;
    }
    __shared__ float t[32][33];
    const float* W = (z==0)?Wq:(z==1)?Wk:(z==2)?Wv:Wo;
    __half* Wt = (z<3) ? (g_wt + (size_t)z*EM*EM) : g_wot;
    int bn = blockIdx.x*32, bk2 = blockIdx.y*32;
    int tx = threadIdx.x & 31, ty = threadIdx.x >> 5;
    #pragma unroll
    for (int i=0;i<32;i+=8)
        t[ty+i][tx] = W[(size_t)(bk2+ty+i)*EM + bn+tx];
    __syncthreads();
    #pragma unroll
    for (int i=0;i<32;i+=8)
        Wt[(size_t)(bn+ty+i)*EM + bk2+tx] = __float2half_rn(t[tx][ty+i]);
}

// ---------------------------------------------------------------------------
// fp16 GEMM: C[128 x 128] tile, K=1024, 4-stage cp.async, ldmatrix + mma16816.
// ---------------------------------------------------------------------------
#define GSTG (128*40*2)       // 10240 B per A or B tile
#define GSMEM (4*2*GSTG)      // 81920

__global__ __launch_bounds__(256,2) void gemm_h(const __half* __restrict__ A,
    const __half* __restrict__ Bt, const float* __restrict__ bias,
    const float* __restrict__ resid, int mode)
{
    extern __shared__ char sm[];
    uint32_t sb = s2u(sm);
    int tid = threadIdx.x, w = tid>>5, lane = tid&31;
    int g = lane>>2, tig = lane&3;
    int rows0 = (w>>2)*64, cols0 = (w&3)*32;
    int m0 = blockIdx.x*128, n0 = blockIdx.y*128;

    float c[4][4][4];
    #pragma unroll
    for (int i=0;i<4;i++)
        #pragma unroll
        for (int j=0;j<4;j++){ c[i][j][0]=0.f; c[i][j][1]=0.f; c[i][j][2]=0.f; c[i][j][3]=0.f; }

    auto load_st = [&](int st, int kc){
        uint32_t base = sb + st*2*GSTG;
        const __half* gA = A + (size_t)m0*EM + kc*32;
        const __half* gB = Bt + (size_t)n0*EM + kc*32;
        #pragma unroll
        for (int i=0;i<2;i++){
            int cix = tid + 256*i;
            int row = cix>>2, part = cix&3;
            cp16(base + row*80 + part*16, gA + (size_t)row*EM + part*8);
        }
        #pragma unroll
        for (int i=0;i<2;i++){
            int cix = tid + 256*i;
            int row = cix>>2, part = cix&3;
            cp16(base + GSTG + row*80 + part*16, gB + (size_t)row*EM + part*8);
        }
    };

    #pragma unroll
    for (int s=0;s<3;s++){ load_st(s, s); cp_commit(); }

    int a_r = lane & 15;
    int a_k = (lane>>4)<<3;
    int b_n = (lane&7) + ((lane>=16)?8:0);
    int b_k = (lane&8)?8:0;

    for (int kc=0; kc<32; kc++){
        if (kc+3 < 32) load_st((kc+3)&3, kc+3);
        cp_commit();
        cp_wait<3>();
        __syncthreads();
        uint32_t Ab = sb + (kc&3)*2*GSTG;
        uint32_t Bb = Ab + GSTG;
        #pragma unroll
        for (int ks=0; ks<2; ks++){
            uint32_t a[4][4];
            #pragma unroll
            for (int mi=0;mi<4;mi++)
                ldsm4(a[mi][0],a[mi][1],a[mi][2],a[mi][3],
                      Ab + (rows0+16*mi+a_r)*80 + (ks*16 + a_k)*2);
            #pragma unroll
            for (int ni2=0;ni2<2;ni2++){
                uint32_t b0,b1,b2,b3;
                ldsm4(b0,b1,b2,b3, Bb + (cols0+16*ni2+b_n)*80 + (ks*16 + b_k)*2);
                #pragma unroll
                for (int mi=0;mi<4;mi++){
                    mmaf16(c[mi][2*ni2],   a[mi], b0, b1);
                    mmaf16(c[mi][2*ni2+1], a[mi], b2, b3);
                }
            }
        }
        __syncthreads();
    }

    #pragma unroll
    for (int mi=0; mi<4; mi++){
        int rowA = rows0 + 16*mi + g;
        int t1 = m0 + rowA, t2 = t1 + 8;
        #pragma unroll
        for (int ni=0; ni<4; ni++){
            int col = cols0 + 8*ni + 2*tig;
            int nglob = n0 + col;
            float bv0 = bias[nglob], bv1 = bias[nglob+1];
            if (mode == 0){
                int mat = nglob>>10, e = nglob&1023, h = e>>6, d = e&63;
                __half* outp = (mat==0) ? g_qh : (mat==1 ? g_kh : g_vh);
                int bb1 = t1>>10, s1 = t1&1023;
                int bb2 = t2>>10, s2 = t2&1023;
                *(__half2*)&outp[(((size_t)(bb1*HN+h))*SQ + s1)*DH + d] =
                    __floats2half2_rn(c[mi][ni][0]+bv0, c[mi][ni][1]+bv1);
                *(__half2*)&outp[(((size_t)(bb2*HN+h))*SQ + s2)*DH + d] =
                    __floats2half2_rn(c[mi][ni][2]+bv0, c[mi][ni][3]+bv1);
            } else {
                const float* r1 = &resid[(size_t)t1*EM + nglob];
                const float* r2 = &resid[(size_t)t2*EM + nglob];
                float2 v1; v1.x = c[mi][ni][0]+bv0+r1[0]; v1.y = c[mi][ni][1]+bv1+r1[1];
                float2 v2; v2.x = c[mi][ni][2]+bv0+r2[0]; v2.y = c[mi][ni][3]+bv1+r2[1];
                *(float2*)&g_h[(size_t)t1*EM + nglob] = v1;
                *(float2*)&g_h[(size_t)t2*EM + nglob] = v2;
            }
        }
    }
}

// ---------------------------------------------------------------------------
// Flash attention, 512 threads, warp pairs, max-free softmax, double-buffered
// K/V, compact QD/KD, D ring. Rel band uses f32-accum mma (fastest path on
// sm_103); D pre-scaled by C2F so rel stores need no multiply.
// ---------------------------------------------------------------------------
#define LDT 144                 // bytes per 64-half row (128 data + 16 pad)
#define LQD 368                 // bytes per compact QD/KD row (184 halves)
#define OQ  0
#define OKA 18432
#define OKB 36864
#define OVA 55296
#define OVB 73728
#define OD  92160               // 256-row ring x 144B
#define OQD 129024              // 128 x LQD   (u = t - 16r)
#define OKD 176128              // 128 x LQD   (v = t - 112 + 16r)
#define OSX 223232
#define ATTN_SMEM 225280

__global__ __launch_bounds__(512,1) void attn_h()
{
    extern __shared__ char sm[];
    uint32_t sb = s2u(sm);

    int bh = blockIdx.x;
    int l0 = blockIdx.y*128;
    int tid = threadIdx.x;
    int w = tid>>5, lane = tid&31, g = lane>>2, tig = lane&3;
    int r = w>>1, wc = w&1;

    int a_r = lane & 15;
    int a_k = (lane>>4)<<3;
    int b_n = (lane&7) + ((lane>=16)?8:0);
    int b_k = (lane&8)?8:0;
    int t_k = (lane&7) + ((lane&8)?8:0);
    int t_n = (lane>=16)?8:0;
    int i0 = 16*r + g;

    // zero logical dist row 255 for rt=0
    if (tid < 9) *(uint4*)(sm + OD + 255*LDT + tid*16) = make_uint4(0,0,0,0);

    // prologue: group A = Q + K0->KA + V0->VA ; group B = D0 (255 rows)
    {
        const __half* qg = g_qh + ((size_t)bh*SQ + l0)*DH;
        const __half* kg = g_kh + ((size_t)bh*SQ)*DH;
        const __half* vg = g_vh + ((size_t)bh*SQ)*DH;
        #pragma unroll
        for (int i=0;i<2;i++){
            int cix = tid + 512*i;
            int row = cix>>3, part = cix&7;
            cp16cg(sb + OQ  + row*LDT + part*16, qg + (size_t)row*DH + part*8);
            cp16cg(sb + OKA + row*LDT + part*16, kg + (size_t)row*DH + part*8);
            cp16cg(sb + OVA + row*LDT + part*16, vg + (size_t)row*DH + part*8);
        }
        cp_commit();
        const __half* dg = g_dist_h + (size_t)(l0 + 896)*DH;
        #pragma unroll
        for (int i=0;i<4;i++){
            int cix = tid + 512*i;
            if (cix < 255*8){
                int row = cix>>3, part = cix&7;
                cp16cg(sb + OD + row*LDT + part*16, dg + (size_t)row*DH + part*8);
            }
        }
        cp_commit();
    }

    float o[8][4];
    #pragma unroll
    for (int i=0;i<8;i++){ o[i][0]=0.f; o[i][1]=0.f; o[i][2]=0.f; o[i][3]=0.f; }
    float lrow0 = 0.f, lrow1 = 0.f;

    uint32_t qa[4][4];
    float* SX = (float*)(sm + OSX);

    for (int rt=0; rt<8; rt++){
        cp_wait<0>();
        __syncthreads();               // K, V (top group) + D (mid group) for rt ready

        uint32_t kb = sb + ((rt&1) ? OKB : OKA);
        uint32_t vb = sb + ((rt&1) ? OVB : OVA);

        if (rt == 0){
            #pragma unroll
            for (int ks=0;ks<4;ks++)
                ldsm4(qa[ks][0],qa[ks][1],qa[ks][2],qa[ks][3],
                      sb + OQ + (16*r+a_r)*LDT + (ks*16 + a_k)*2);
        }
        if (rt < 7){                   // prefetch K,V for rt+1 into the other buffers
            uint32_t kn = sb + ((rt&1) ? OKA : OKB);
            uint32_t vn = sb + ((rt&1) ? OVA : OVB);
            const __half* kg = g_kh + ((size_t)bh*SQ + (rt+1)*128)*DH;
            const __half* vg = g_vh + ((size_t)bh*SQ + (rt+1)*128)*DH;
            #pragma unroll
            for (int i=0;i<2;i++){
                int cix = tid + 512*i;
                int row = cix>>3, part = cix&7;
                cp16cg(kn + row*LDT + part*16, kg + (size_t)row*DH + part*8);
                cp16cg(vn + row*LDT + part*16, vg + (size_t)row*DH + part*8);
            }
            cp_commit();
        }

        int rowoff = (rt & 1) << 7;    // D ring offset

        // ---- QD tiles (pair covers [r..r+8]); store at [i][t-16r] ----
        {
            int T0 = wc ? r : (r+5);
            int nT = wc ? 5 : 4;
            for (int ti=0; ti<nT; ti++){
                int t0r = (T0+ti)<<4;
                int u0 = t0r - 16*r;
                uint32_t dbase = sb + OD + (((t0r + b_n) + rowoff) & 255)*LDT;
                float qd[2][4];
                qd[0][0]=0.f;qd[0][1]=0.f;qd[0][2]=0.f;qd[0][3]=0.f;
                qd[1][0]=0.f;qd[1][1]=0.f;qd[1][2]=0.f;qd[1][3]=0.f;
                #pragma unroll
                for (int ks=0;ks<4;ks++){
                    uint32_t b0,b1,b2,b3;
                    ldsm4(b0,b1,b2,b3, dbase + (ks*16 + b_k)*2);
                    mmaf16(qd[0], qa[ks], b0, b1);
                    mmaf16(qd[1], qa[ks], b2, b3);
                }
                #pragma unroll
                for (int f=0;f<2;f++){
                    int u = u0 + 8*f + 2*tig;
                    *(__half2*)(sm + OQD + (size_t)i0*LQD + u*2)     = __floats2half2_rn(qd[f][0], qd[f][1]);
                    *(__half2*)(sm + OQD + (size_t)(i0+8)*LQD + u*2) = __floats2half2_rn(qd[f][2], qd[f][3]);
                }
            }
        }

        // ---- ka fragments (feed only KD) ----
        uint32_t ka[4][4];
        #pragma unroll
        for (int ks=0;ks<4;ks++)
            ldsm4(ka[ks][0],ka[ks][1],ka[ks][2],ka[ks][3],
                  kb + (16*r+a_r)*LDT + (ks*16 + a_k)*2);

        // ---- KD tiles (pair covers [7-r..15-r]); store at [j][t-112+16r] ----
        {
            int T0 = wc ? (7-r) : (12-r);
            int nT = wc ? 5 : 4;
            for (int ti=0; ti<nT; ti++){
                int t0r = (T0+ti)<<4;
                int v0 = t0r - 112 + 16*r;
                uint32_t dbase = sb + OD + (((t0r + b_n) + rowoff) & 255)*LDT;
                float kd[2][4];
                kd[0][0]=0.f;kd[0][1]=0.f;kd[0][2]=0.f;kd[0][3]=0.f;
                kd[1][0]=0.f;kd[1][1]=0.f;kd[1][2]=0.f;kd[1][3]=0.f;
                #pragma unroll
                for (int ks=0;ks<4;ks++){
                    uint32_t b0,b1,b2,b3;
                    ldsm4(b0,b1,b2,b3, dbase + (ks*16 + b_k)*2);
                    mmaf16(kd[0], ka[ks], b0, b1);
                    mmaf16(kd[1], ka[ks], b2, b3);
                }
                #pragma unroll
                for (int f=0;f<2;f++){
                    int v = v0 + 8*f + 2*tig;
                    *(__half2*)(sm + OKD + (size_t)i0*LQD + v*2)     = __floats2half2_rn(kd[f][0], kd[f][1]);
                    *(__half2*)(sm + OKD + (size_t)(i0+8)*LQD + v*2) = __floats2half2_rn(kd[f][2], kd[f][3]);
                }
            }
        }

        // ---- S = Q @ K^T (warp tile 16 x 64: cols [64wc, 64wc+64)) ----
        float cs[8][4];
        #pragma unroll
        for (int f=0;f<8;f++){ cs[f][0]=0.f; cs[f][1]=0.f; cs[f][2]=0.f; cs[f][3]=0.f; }
        #pragma unroll
        for (int ks=0;ks<4;ks++){
            #pragma unroll
            for (int ntl=0;ntl<4;ntl++){
                uint32_t b0,b1,b2,b3;
                ldsm4(b0,b1,b2,b3, kb + (16*(4*wc+ntl)+b_n)*LDT + (ks*16 + b_k)*2);
                mmaf16(cs[2*ntl],   qa[ks], b0, b1);
                mmaf16(cs[2*ntl+1], qa[ks], b2, b3);
            }
        }

        __syncthreads();               // QD/KD STS visible; D ring reads done

        if (rt < 7){                   // prefetch D(rt+1) into free ring half
            int poff = ((rt+1) & 1) << 7;
            const __half* dg = g_dist_h + (size_t)(l0 - (rt+1)*128 + 896)*DH;
            #pragma unroll
            for (int i=0;i<2;i++){
                int cix = tid + 512*i;
                int row = cix>>3, part = cix&7;
                cp16cg(sb + OD + (row + poff)*LDT + part*16, dg + (size_t)row*DH + part*8);
            }
            cp_commit();
        }

        // ---- max-free softmax: gather from compact layouts, exp2, pack ----
        {
            const char* QDb = sm + OQD;
            const char* KDb = sm + OKD;
            uint32_t p[8][2];
            #pragma unroll
            for (int f=0;f<8;f++){
                int j = 64*wc + 8*f + 2*tig;
                int uq = g + 127 - j;              // QD col for (i0, j)
                int jl = (8*f + 2*tig) & 15;
                int v00 = i0 + 15 - jl;            // KD col for (row j, i0)
                float b00 = __half2float(*(const __half*)(QDb + (size_t)i0*LQD + uq*2))
                          + __half2float(*(const __half*)(KDb + (size_t)j*LQD + v00*2));
                float b01 = __half2float(*(const __half*)(QDb + (size_t)i0*LQD + (uq-1)*2))
                          + __half2float(*(const __half*)(KDb + (size_t)(j+1)*LQD + (v00-1)*2));
                float b10 = __half2float(*(const __half*)(QDb + (size_t)(i0+8)*LQD + (uq+8)*2))
                          + __half2float(*(const __half*)(KDb + (size_t)j*LQD + (v00+8)*2));
                float b11 = __half2float(*(const __half*)(QDb + (size_t)(i0+8)*LQD + (uq+7)*2))
                          + __half2float(*(const __half*)(KDb + (size_t)(j+1)*LQD + (v00+7)*2));
                float p00 = ex2(fmaf(cs[f][0], C2F, b00));
                float p01 = ex2(fmaf(cs[f][1], C2F, b01));
                float p10 = ex2(fmaf(cs[f][2], C2F, b10));
                float p11 = ex2(fmaf(cs[f][3], C2F, b11));
                lrow0 += p00 + p01; lrow1 += p10 + p11;
                __half2 hA = __floats2half2_rn(p00, p01); p[f][0] = *(uint32_t*)&hA;
                __half2 hB = __floats2half2_rn(p10, p11); p[f][1] = *(uint32_t*)&hB;
            }

            // ---- O += P @ V over this warp's 64-key slice ----
            #pragma unroll
            for (int kl=0;kl<4;kl++){
                int kk = 4*wc + kl;
                uint32_t a[4] = { p[2*kl][0], p[2*kl][1], p[2*kl+1][0], p[2*kl+1][1] };
                #pragma unroll
                for (int ni2=0;ni2<4;ni2++){
                    uint32_t v0,v1,v2,v3;
                    ldsm4t(v0,v1,v2,v3, vb + (16*kk + t_k)*LDT + (16*ni2 + t_n)*2);
                    mmaf16(o[2*ni2],   a, v0, v1);
                    mmaf16(o[2*ni2+1], a, v2, v3);
                }
            }
        }
        // no end barrier: next iter's top barrier protects all buffers
    }

    // ---- epilogue: reduce l, pair-sum partial O (QD region reused), write ctx ----
    lrow0 += __shfl_xor_sync(0xffffffffu, lrow0, 1);
    lrow0 += __shfl_xor_sync(0xffffffffu, lrow0, 2);
    lrow1 += __shfl_xor_sync(0xffffffffu, lrow1, 1);
    lrow1 += __shfl_xor_sync(0xffffffffu, lrow1, 2);
    SX[i0*2 + wc]     = lrow0;
    SX[(i0+8)*2 + wc] = lrow1;
    barp(1 + r);                       // partner's last gather reads done

    float* OS = (float*)(sm + OQD);    // [128][66] floats fits in QD region
    if (wc == 0){
        #pragma unroll
        for (int ni=0; ni<8; ni++){
            int d = 8*ni + 2*tig;
            OS[i0*66 + d]       = o[ni][0];
            OS[i0*66 + d + 1]   = o[ni][1];
            OS[(i0+8)*66 + d]   = o[ni][2];
            OS[(i0+8)*66 + d+1] = o[ni][3];
        }
    }
    barp(1 + r);
    if (wc == 1){
        float lt0 = lrow0 + SX[i0*2 + 0];
        float lt1 = lrow1 + SX[(i0+8)*2 + 0];
        float inv0 = 1.f / lt0;
        float inv1 = 1.f / lt1;
        int bb = bh>>4, hh = bh&15;
        int s1r = l0 + i0;
        __half* base1 = g_ctx_h + ((size_t)(bb*SQ + s1r  ))*EM + hh*DH;
        __half* base2 = g_ctx_h + ((size_t)(bb*SQ + s1r+8))*EM + hh*DH;
        #pragma unroll
        for (int ni=0; ni<8; ni++){
            int d = 8*ni + 2*tig;
            float v0 = (o[ni][0] + OS[i0*66 + d])       * inv0;
            float v1 = (o[ni][1] + OS[i0*66 + d + 1])   * inv0;
            float v2 = (o[ni][2] + OS[(i0+8)*66 + d])   * inv1;
            float v3 = (o[ni][3] + OS[(i0+8)*66 + d+1]) * inv1;
            *(__half2*)&base1[d] = __floats2half2_rn(v0, v1);
            *(__half2*)&base2[d] = __floats2half2_rn(v2, v3);
        }
    }
}

// ---------------------------------------------------------------------------
// LayerNorm: 512 threads, 2 rows per block
// ---------------------------------------------------------------------------
__global__ __launch_bounds__(512) void ln_kernel(const float* __restrict__ gamma,
    const float* __restrict__ beta, float* __restrict__ out)
{
    int hf = threadIdx.x >> 8;           // 0/1: which row
    int tid = threadIdx.x & 255;
    int row = blockIdx.x*2 + hf;
    int w = tid>>5, lane = tid&31;
    const float4 x4 = ((const float4*)(g_h + (size_t)row*EM))[tid];
    float s = x4.x + x4.y + x4.z + x4.w;
    float q = x4.x*x4.x + x4.y*x4.y + x4.z*x4.z + x4.w*x4.w;
    #pragma unroll
    for (int off=16; off; off>>=1){
        s += __shfl_xor_sync(0xffffffffu, s, off);
        q += __shfl_xor_sync(0xffffffffu, q, off);
    }
    __shared__ float ss[2][8], qs[2][8];
    __shared__ float mean_s[2], rs_s[2];
    if (lane==0){ ss[hf][w]=s; qs[hf][w]=q; }
    __syncthreads();
    if (w==0){
        float s2 = (lane<8) ? ss[hf][lane] : 0.f;
        float q2 = (lane<8) ? qs[hf][lane] : 0.f;
        #pragma unroll
        for (int off=4; off; off>>=1){
            s2 += __shfl_xor_sync(0xffffffffu, s2, off);
            q2 += __shfl_xor_sync(0xffffffffu, q2, off);
        }
        if (lane==0){
            float mean = s2 * (1.f/1024.f);
            float var  = fmaxf(q2 * (1.f/1024.f) - mean*mean, 0.f);
            mean_s[hf] = mean;
            rs_s[hf]   = rsqrtf(var + 1e-12f);
        }
    }
    __syncthreads();
    float mean = mean_s[hf], rs = rs_s[hf];
    float4 gm = ((const float4*)gamma)[tid];
    float4 bt = ((const float4*)beta)[tid];
    float4 y;
    y.x = (x4.x - mean)*rs*gm.x + bt.x;
    y.y = (x4.y - mean)*rs*gm.y + bt.y;
    y.z = (x4.z - mean)*rs*gm.z + bt.z;
    y.w = (x4.w - mean)*rs*gm.w + bt.w;
    ((float4*)(out + (size_t)row*EM))[tid] = y;
}

// ---------------------------------------------------------------------------
extern "C" void kernel_launch(void* const* d_in, const int* in_sizes, int n_in,
                              void* d_out, int out_size)
{
    const float* hidden = (const float*)d_in[0];
    const float* Wq  = (const float*)d_in[1];
    const float* bq  = (const float*)d_in[2];
    const float* Wk  = (const float*)d_in[3];
    const float* bk  = (const float*)d_in[4];
    const float* Wv  = (const float*)d_in[5];
    const float* bv  = (const float*)d_in[6];
    const float* dist= (const float*)d_in[7];
    const float* Wo  = (const float*)d_in[8];
    const float* bo  = (const float*)d_in[9];
    const float* gam = (const float*)d_in[10];
    const float* bet = (const float*)d_in[11];
    float* out = (float*)d_out;

    cudaFuncSetAttribute(attn_h, cudaFuncAttributeMaxDynamicSharedMemorySize, ATTN_SMEM);
    cudaFuncSetAttribute(gemm_h, cudaFuncAttributeMaxDynamicSharedMemorySize, GSMEM);

    __half *hidh, *wt, *wot, *ctxh;
    float *biasq;
    cudaGetSymbolAddress((void**)&hidh,  g_hid_h);
    cudaGetSymbolAddress((void**)&wt,    g_wt);
    cudaGetSymbolAddress((void**)&wot,   g_wot);
    cudaGetSymbolAddress((void**)&ctxh,  g_ctx_h);
    cudaGetSymbolAddress((void**)&biasq, g_biasqkv);

    // launch order puts attn_h at index 3 (the launch ncu captures)
    pack_h_kernel<<<NTOK*EM/4/256, 256>>>(hidden, hidh, NTOK*EM/4);          // 0
    pack_wt_all<<<dim3(32,32,5), 256>>>(Wq, Wk, Wv, Wo, dist, bq, bk, bv);   // 1
    gemm_h<<<dim3(64,24), 256, GSMEM>>>(hidh, wt, biasq, nullptr, 0);        // 2
    attn_h<<<dim3(128,8), 512, ATTN_SMEM>>>();                               // 3 <- ncu
    gemm_h<<<dim3(64,8), 256, GSMEM>>>(ctxh, wot, bo, hidden, 1);            // 4
    ln_kernel<<<NTOK/2, 512>>>(gam, bet, out);                               // 5
}

// round 15
// speedup vs baseline: 1.5649x; 1.0209x over previous
#include <cuda_runtime.h>
#include <cuda_fp16.h>
#include <cstdint>

#define HN 16
#define DH 64
#define EM 1024
#define SQ 1024
#define BA 8
#define BH (BA*HN)
#define NTOK (BA*SQ)

// Scratch (device globals; allocation-free per harness rules)
__device__ __half g_hid_h[NTOK*EM];
__device__ __half g_wt[3*EM*EM];      // [3072 n][1024 k] (W^T, fp16)
__device__ __half g_wot[EM*EM];       // [1024 n][1024 k]
__device__ __half g_qh[BH*SQ*DH];
__device__ __half g_kh[BH*SQ*DH];
__device__ __half g_vh[BH*SQ*DH];
__device__ __half g_ctx_h[NTOK*EM];
__device__ __half g_dist_h[2047*DH];  // pre-scaled by C2F
__device__ float  g_biasqkv[3*EM];
__device__ float  g_h[NTOK*EM];

// ---------------------------------------------------------------------------
// PTX helpers (all non-'a' features: sm_80-class, compile at sm_103)
// ---------------------------------------------------------------------------
__device__ __forceinline__ uint32_t s2u(const void* p){
    uint32_t a; asm("{ .reg .u64 t; cvta.to.shared.u64 t, %1; cvt.u32.u64 %0, t; }" : "=r"(a) : "l"(p)); return a;
}
__device__ __forceinline__ void ldsm4(uint32_t& r0, uint32_t& r1, uint32_t& r2, uint32_t& r3, uint32_t addr){
    asm volatile("ldmatrix.sync.aligned.m8n8.x4.shared.b16 {%0,%1,%2,%3}, [%4];"
        : "=r"(r0), "=r"(r1), "=r"(r2), "=r"(r3) : "r"(addr));
}
__device__ __forceinline__ void ldsm4t(uint32_t& r0, uint32_t& r1, uint32_t& r2, uint32_t& r3, uint32_t addr){
    asm volatile("ldmatrix.sync.aligned.m8n8.x4.trans.shared.b16 {%0,%1,%2,%3}, [%4];"
        : "=r"(r0), "=r"(r1), "=r"(r2), "=r"(r3) : "r"(addr));
}
__device__ __forceinline__ void mmaf16(float c[4], const uint32_t a[4], uint32_t b0, uint32_t b1){
    asm volatile("mma.sync.aligned.m16n8k16.row.col.f32.f16.f16.f32 "
        "{%0,%1,%2,%3}, {%4,%5,%6,%7}, {%8,%9}, {%0,%1,%2,%3};"
        : "+f"(c[0]), "+f"(c[1]), "+f"(c[2]), "+f"(c[3])
        : "r"(a[0]), "r"(a[1]), "r"(a[2]), "r"(a[3]), "r"(b0), "r"(b1));
}
__device__ __forceinline__ void cp16(uint32_t dst, const void* src){
    asm volatile("cp.async.ca.shared.global [%0], [%1], 16;" :: "r"(dst), "l"(src));
}
__device__ __forceinline__ void cp16cg(uint32_t dst, const void* src){
    asm volatile("cp.async.cg.shared.global [%0], [%1], 16;" :: "r"(dst), "l"(src));
}
__device__ __forceinline__ void cp_commit(){ asm volatile("cp.async.commit_group;" ::: "memory"); }
template<int N> __device__ __forceinline__ void cp_wait(){
    asm volatile("cp.async.wait_group %0;" :: "n"(N) : "memory");
}
__device__ __forceinline__ float ex2(float x){
    float y; asm("ex2.approx.f32 %0, %1;" : "=f"(y) : "f"(x)); return y;
}
__device__ __forceinline__ void barp(int id){
    asm volatile("bar.sync %0, 64;" :: "r"(id) : "memory");
}

#define C2F 0.18033688f         // 0.125 * log2(e)

// ---------------------------------------------------------------------------
// Pack kernels
// ---------------------------------------------------------------------------
__global__ __launch_bounds__(256) void pack_h_kernel(const float* __restrict__ src,
                                                     __half* __restrict__ dst, int n4)
{
    int i = blockIdx.x*256 + threadIdx.x;
    if (i < n4){
        float4 v = ((const float4*)src)[i];
        __half2* d = (__half2*)dst + i*2;
        d[0] = __floats2half2_rn(v.x, v.y);
        d[1] = __floats2half2_rn(v.z, v.w);
    }
}

// z=0..3: weight transposes Wq,Wk,Wv,Wo.  z=4: dist fp16 pack (pre-scaled by C2F) + bias copy.
__global__ __launch_bounds__(256) void pack_wt_all(const float* __restrict__ Wq,
    const float* __restrict__ Wk, const float* __restrict__ Wv,
    const float* __restrict__ Wo, const float* __restrict__ dist,
    const float* __restrict__ bq, const float* __restrict__ bk,
    const float* __restrict__ bv)
{
    int z = blockIdx.z;
    if (z == 4){
        int bid = blockIdx.y*32 + blockIdx.x;
        int i = bid*256 + threadIdx.x;
        const int ND4 = 2047*DH/4;           // 32752 float4 of dist
        if (i < ND4){
            float4 v = ((const float4*)dist)[i];
            __half2* d = (__half2*)g_dist_h + i*2;
            d[0] = __floats2half2_rn(v.x*C2F, v.y*C2F);
            d[1] = __floats2half2_rn(v.z*C2F, v.w*C2F);
        } else {
            int j = i - ND4;
            if (j < 3*EM){
                int b = j >> 10, e = j & 1023;
                const float* s = (b==0) ? bq : (b==1 ? bk : bv);
                g_biasqkv[j] = s[e];
            }
        }
        return;
    }
    __shared__ float t[32][33];
    const float* W = (z==0)?Wq:(z==1)?Wk:(z==2)?Wv:Wo;
    __half* Wt = (z<3) ? (g_wt + (size_t)z*EM*EM) : g_wot;
    int bn = blockIdx.x*32, bk2 = blockIdx.y*32;
    int tx = threadIdx.x & 31, ty = threadIdx.x >> 5;
    #pragma unroll
    for (int i=0;i<32;i+=8)
        t[ty+i][tx] = W[(size_t)(bk2+ty+i)*EM + bn+tx];
    __syncthreads();
    #pragma unroll
    for (int i=0;i<32;i+=8)
        Wt[(size_t)(bn+ty+i)*EM + bk2+tx] = __float2half_rn(t[tx][ty+i]);
}

// ---------------------------------------------------------------------------
// fp16 GEMM: C[128 x 128] tile, K=1024 in 16 chunks of 64, 3-stage cp.async
// pipeline (stage rows 144B, conflict-free), ldmatrix + mma16816.
// Halves barrier count vs 32x k32 chunks; 2x work per iteration.
// ---------------------------------------------------------------------------
#define GLD2 144               // bytes per 64-half row (128 data + 16 pad)
#define GSTG2 (128*GLD2)       // 18432 B per matrix per stage
#define GSMEM (3*2*GSTG2)      // 110592

__global__ __launch_bounds__(256,2) void gemm_h(const __half* __restrict__ A,
    const __half* __restrict__ Bt, const float* __restrict__ bias,
    const float* __restrict__ resid, int mode)
{
    extern __shared__ char sm[];
    uint32_t sb = s2u(sm);
    int tid = threadIdx.x, w = tid>>5, lane = tid&31;
    int g = lane>>2, tig = lane&3;
    int rows0 = (w>>2)*64, cols0 = (w&3)*32;
    int m0 = blockIdx.x*128, n0 = blockIdx.y*128;

    float c[4][4][4];
    #pragma unroll
    for (int i=0;i<4;i++)
        #pragma unroll
        for (int j=0;j<4;j++){ c[i][j][0]=0.f; c[i][j][1]=0.f; c[i][j][2]=0.f; c[i][j][3]=0.f; }

    auto load_st = [&](int st, int kc){      // kc in units of 64
        uint32_t base = sb + st*2*GSTG2;
        const __half* gA = A + (size_t)m0*EM + kc*64;
        const __half* gB = Bt + (size_t)n0*EM + kc*64;
        #pragma unroll
        for (int i=0;i<4;i++){
            int cix = tid + 256*i;
            int row = cix>>3, part = cix&7;
            cp16(base + row*GLD2 + part*16, gA + (size_t)row*EM + part*8);
        }
        #pragma unroll
        for (int i=0;i<4;i++){
            int cix = tid + 256*i;
            int row = cix>>3, part = cix&7;
            cp16(base + GSTG2 + row*GLD2 + part*16, gB + (size_t)row*EM + part*8);
        }
    };

    load_st(0, 0); cp_commit();
    load_st(1, 1); cp_commit();

    int a_r = lane & 15;
    int a_k = (lane>>4)<<3;
    int b_n = (lane&7) + ((lane>=16)?8:0);
    int b_k = (lane&8)?8:0;

    for (int kc=0; kc<16; kc++){
        if (kc+2 < 16) load_st((kc+2)%3, kc+2);
        cp_commit();
        cp_wait<2>();
        __syncthreads();
        uint32_t Ab = sb + (kc%3)*2*GSTG2;
        uint32_t Bb = Ab + GSTG2;
        #pragma unroll
        for (int ks=0; ks<4; ks++){
            uint32_t a[4][4];
            #pragma unroll
            for (int mi=0;mi<4;mi++)
                ldsm4(a[mi][0],a[mi][1],a[mi][2],a[mi][3],
                      Ab + (rows0+16*mi+a_r)*GLD2 + (ks*16 + a_k)*2);
            #pragma unroll
            for (int ni2=0;ni2<2;ni2++){
                uint32_t b0,b1,b2,b3;
                ldsm4(b0,b1,b2,b3, Bb + (cols0+16*ni2+b_n)*GLD2 + (ks*16 + b_k)*2);
                #pragma unroll
                for (int mi=0;mi<4;mi++){
                    mmaf16(c[mi][2*ni2],   a[mi], b0, b1);
                    mmaf16(c[mi][2*ni2+1], a[mi], b2, b3);
                }
            }
        }
        __syncthreads();
    }

    #pragma unroll
    for (int mi=0; mi<4; mi++){
        int rowA = rows0 + 16*mi + g;
        int t1 = m0 + rowA, t2 = t1 + 8;
        #pragma unroll
        for (int ni=0; ni<4; ni++){
            int col = cols0 + 8*ni + 2*tig;
            int nglob = n0 + col;
            float bv0 = bias[nglob], bv1 = bias[nglob+1];
            if (mode == 0){
                int mat = nglob>>10, e = nglob&1023, h = e>>6, d = e&63;
                __half* outp = (mat==0) ? g_qh : (mat==1 ? g_kh : g_vh);
                int bb1 = t1>>10, s1 = t1&1023;
                int bb2 = t2>>10, s2 = t2&1023;
                *(__half2*)&outp[(((size_t)(bb1*HN+h))*SQ + s1)*DH + d] =
                    __floats2half2_rn(c[mi][ni][0]+bv0, c[mi][ni][1]+bv1);
                *(__half2*)&outp[(((size_t)(bb2*HN+h))*SQ + s2)*DH + d] =
                    __floats2half2_rn(c[mi][ni][2]+bv0, c[mi][ni][3]+bv1);
            } else {
                const float* r1 = &resid[(size_t)t1*EM + nglob];
                const float* r2 = &resid[(size_t)t2*EM + nglob];
                float2 v1; v1.x = c[mi][ni][0]+bv0+r1[0]; v1.y = c[mi][ni][1]+bv1+r1[1];
                float2 v2; v2.x = c[mi][ni][2]+bv0+r2[0]; v2.y = c[mi][ni][3]+bv1+r2[1];
                *(float2*)&g_h[(size_t)t1*EM + nglob] = v1;
                *(float2*)&g_h[(size_t)t2*EM + nglob] = v2;
            }
        }
    }
}

// ---------------------------------------------------------------------------
// Flash attention, 512 threads, warp pairs, max-free softmax, double-buffered
// K/V, compact QD/KD, D ring. (unchanged from 566.7us champion)
// ---------------------------------------------------------------------------
#define LDT 144                 // bytes per 64-half row (128 data + 16 pad)
#define LQD 368                 // bytes per compact QD/KD row (184 halves)
#define OQ  0
#define OKA 18432
#define OKB 36864
#define OVA 55296
#define OVB 73728
#define OD  92160               // 256-row ring x 144B
#define OQD 129024              // 128 x LQD   (u = t - 16r)
#define OKD 176128              // 128 x LQD   (v = t - 112 + 16r)
#define OSX 223232
#define ATTN_SMEM 225280

__global__ __launch_bounds__(512,1) void attn_h()
{
    extern __shared__ char sm[];
    uint32_t sb = s2u(sm);

    int bh = blockIdx.x;
    int l0 = blockIdx.y*128;
    int tid = threadIdx.x;
    int w = tid>>5, lane = tid&31, g = lane>>2, tig = lane&3;
    int r = w>>1, wc = w&1;

    int a_r = lane & 15;
    int a_k = (lane>>4)<<3;
    int b_n = (lane&7) + ((lane>=16)?8:0);
    int b_k = (lane&8)?8:0;
    int t_k = (lane&7) + ((lane&8)?8:0);
    int t_n = (lane>=16)?8:0;
    int i0 = 16*r + g;

    // zero logical dist row 255 for rt=0
    if (tid < 9) *(uint4*)(sm + OD + 255*LDT + tid*16) = make_uint4(0,0,0,0);

    // prologue: group A = Q + K0->KA + V0->VA ; group B = D0 (255 rows)
    {
        const __half* qg = g_qh + ((size_t)bh*SQ + l0)*DH;
        const __half* kg = g_kh + ((size_t)bh*SQ)*DH;
        const __half* vg = g_vh + ((size_t)bh*SQ)*DH;
        #pragma unroll
        for (int i=0;i<2;i++){
            int cix = tid + 512*i;
            int row = cix>>3, part = cix&7;
            cp16cg(sb + OQ  + row*LDT + part*16, qg + (size_t)row*DH + part*8);
            cp16cg(sb + OKA + row*LDT + part*16, kg + (size_t)row*DH + part*8);
            cp16cg(sb + OVA + row*LDT + part*16, vg + (size_t)row*DH + part*8);
        }
        cp_commit();
        const __half* dg = g_dist_h + (size_t)(l0 + 896)*DH;
        #pragma unroll
        for (int i=0;i<4;i++){
            int cix = tid + 512*i;
            if (cix < 255*8){
                int row = cix>>3, part = cix&7;
                cp16cg(sb + OD + row*LDT + part*16, dg + (size_t)row*DH + part*8);
            }
        }
        cp_commit();
    }

    float o[8][4];
    #pragma unroll
    for (int i=0;i<8;i++){ o[i][0]=0.f; o[i][1]=0.f; o[i][2]=0.f; o[i][3]=0.f; }
    float lrow0 = 0.f, lrow1 = 0.f;

    uint32_t qa[4][4];
    float* SX = (float*)(sm + OSX);

    for (int rt=0; rt<8; rt++){
        cp_wait<0>();
        __syncthreads();               // K, V (top group) + D (mid group) for rt ready

        uint32_t kb = sb + ((rt&1) ? OKB : OKA);
        uint32_t vb = sb + ((rt&1) ? OVB : OVA);

        if (rt == 0){
            #pragma unroll
            for (int ks=0;ks<4;ks++)
                ldsm4(qa[ks][0],qa[ks][1],qa[ks][2],qa[ks][3],
                      sb + OQ + (16*r+a_r)*LDT + (ks*16 + a_k)*2);
        }
        if (rt < 7){                   // prefetch K,V for rt+1 into the other buffers
            uint32_t kn = sb + ((rt&1) ? OKA : OKB);
            uint32_t vn = sb + ((rt&1) ? OVA : OVB);
            const __half* kg = g_kh + ((size_t)bh*SQ + (rt+1)*128)*DH;
            const __half* vg = g_vh + ((size_t)bh*SQ + (rt+1)*128)*DH;
            #pragma unroll
            for (int i=0;i<2;i++){
                int cix = tid + 512*i;
                int row = cix>>3, part = cix&7;
                cp16cg(kn + row*LDT + part*16, kg + (size_t)row*DH + part*8);
                cp16cg(vn + row*LDT + part*16, vg + (size_t)row*DH + part*8);
            }
            cp_commit();
        }

        int rowoff = (rt & 1) << 7;    // D ring offset

        // ---- QD tiles (pair covers [r..r+8]); store at [i][t-16r] ----
        {
            int T0 = wc ? r : (r+5);
            int nT = wc ? 5 : 4;
            for (int ti=0; ti<nT; ti++){
                int t0r = (T0+ti)<<4;
                int u0 = t0r - 16*r;
                uint32_t dbase = sb + OD + (((t0r + b_n) + rowoff) & 255)*LDT;
                float qd[2][4];
                qd[0][0]=0.f;qd[0][1]=0.f;qd[0][2]=0.f;qd[0][3]=0.f;
                qd[1][0]=0.f;qd[1][1]=0.f;qd[1][2]=0.f;qd[1][3]=0.f;
                #pragma unroll
                for (int ks=0;ks<4;ks++){
                    uint32_t b0,b1,b2,b3;
                    ldsm4(b0,b1,b2,b3, dbase + (ks*16 + b_k)*2);
                    mmaf16(qd[0], qa[ks], b0, b1);
                    mmaf16(qd[1], qa[ks], b2, b3);
                }
                #pragma unroll
                for (int f=0;f<2;f++){
                    int u = u0 + 8*f + 2*tig;
                    *(__half2*)(sm + OQD + (size_t)i0*LQD + u*2)     = __floats2half2_rn(qd[f][0], qd[f][1]);
                    *(__half2*)(sm + OQD + (size_t)(i0+8)*LQD + u*2) = __floats2half2_rn(qd[f][2], qd[f][3]);
                }
            }
        }

        // ---- ka fragments (feed only KD) ----
        uint32_t ka[4][4];
        #pragma unroll
        for (int ks=0;ks<4;ks++)
            ldsm4(ka[ks][0],ka[ks][1],ka[ks][2],ka[ks][3],
                  kb + (16*r+a_r)*LDT + (ks*16 + a_k)*2);

        // ---- KD tiles (pair covers [7-r..15-r]); store at [j][t-112+16r] ----
        {
            int T0 = wc ? (7-r) : (12-r);
            int nT = wc ? 5 : 4;
            for (int ti=0; ti<nT; ti++){
                int t0r = (T0+ti)<<4;
                int v0 = t0r - 112 + 16*r;
                uint32_t dbase = sb + OD + (((t0r + b_n) + rowoff) & 255)*LDT;
                float kd[2][4];
                kd[0][0]=0.f;kd[0][1]=0.f;kd[0][2]=0.f;kd[0][3]=0.f;
                kd[1][0]=0.f;kd[1][1]=0.f;kd[1][2]=0.f;kd[1][3]=0.f;
                #pragma unroll
                for (int ks=0;ks<4;ks++){
                    uint32_t b0,b1,b2,b3;
                    ldsm4(b0,b1,b2,b3, dbase + (ks*16 + b_k)*2);
                    mmaf16(kd[0], ka[ks], b0, b1);
                    mmaf16(kd[1], ka[ks], b2, b3);
                }
                #pragma unroll
                for (int f=0;f<2;f++){
                    int v = v0 + 8*f + 2*tig;
                    *(__half2*)(sm + OKD + (size_t)i0*LQD + v*2)     = __floats2half2_rn(kd[f][0], kd[f][1]);
                    *(__half2*)(sm + OKD + (size_t)(i0+8)*LQD + v*2) = __floats2half2_rn(kd[f][2], kd[f][3]);
                }
            }
        }

        // ---- S = Q @ K^T (warp tile 16 x 64: cols [64wc, 64wc+64)) ----
        float cs[8][4];
        #pragma unroll
        for (int f=0;f<8;f++){ cs[f][0]=0.f; cs[f][1]=0.f; cs[f][2]=0.f; cs[f][3]=0.f; }
        #pragma unroll
        for (int ks=0;ks<4;ks++){
            #pragma unroll
            for (int ntl=0;ntl<4;ntl++){
                uint32_t b0,b1,b2,b3;
                ldsm4(b0,b1,b2,b3, kb + (16*(4*wc+ntl)+b_n)*LDT + (ks*16 + b_k)*2);
                mmaf16(cs[2*ntl],   qa[ks], b0, b1);
                mmaf16(cs[2*ntl+1], qa[ks], b2, b3);
            }
        }

        __syncthreads();               // QD/KD STS visible; D ring reads done

        if (rt < 7){                   // prefetch D(rt+1) into free ring half
            int poff = ((rt+1) & 1) << 7;
            const __half* dg = g_dist_h + (size_t)(l0 - (rt+1)*128 + 896)*DH;
            #pragma unroll
            for (int i=0;i<2;i++){
                int cix = tid + 512*i;
                int row = cix>>3, part = cix&7;
                cp16cg(sb + OD + (row + poff)*LDT + part*16, dg + (size_t)row*DH + part*8);
            }
            cp_commit();
        }

        // ---- max-free softmax: gather from compact layouts, exp2, pack ----
        {
            const char* QDb = sm + OQD;
            const char* KDb = sm + OKD;
            uint32_t p[8][2];
            #pragma unroll
            for (int f=0;f<8;f++){
                int j = 64*wc + 8*f + 2*tig;
                int uq = g + 127 - j;              // QD col for (i0, j)
                int jl = (8*f + 2*tig) & 15;
                int v00 = i0 + 15 - jl;            // KD col for (row j, i0)
                float b00 = __half2float(*(const __half*)(QDb + (size_t)i0*LQD + uq*2))
                          + __half2float(*(const __half*)(KDb + (size_t)j*LQD + v00*2));
                float b01 = __half2float(*(const __half*)(QDb + (size_t)i0*LQD + (uq-1)*2))
                          + __half2float(*(const __half*)(KDb + (size_t)(j+1)*LQD + (v00-1)*2));
                float b10 = __half2float(*(const __half*)(QDb + (size_t)(i0+8)*LQD + (uq+8)*2))
                          + __half2float(*(const __half*)(KDb + (size_t)j*LQD + (v00+8)*2));
                float b11 = __half2float(*(const __half*)(QDb + (size_t)(i0+8)*LQD + (uq+7)*2))
                          + __half2float(*(const __half*)(KDb + (size_t)(j+1)*LQD + (v00+7)*2));
                float p00 = ex2(fmaf(cs[f][0], C2F, b00));
                float p01 = ex2(fmaf(cs[f][1], C2F, b01));
                float p10 = ex2(fmaf(cs[f][2], C2F, b10));
                float p11 = ex2(fmaf(cs[f][3], C2F, b11));
                lrow0 += p00 + p01; lrow1 += p10 + p11;
                __half2 hA = __floats2half2_rn(p00, p01); p[f][0] = *(uint32_t*)&hA;
                __half2 hB = __floats2half2_rn(p10, p11); p[f][1] = *(uint32_t*)&hB;
            }

            // ---- O += P @ V over this warp's 64-key slice ----
            #pragma unroll
            for (int kl=0;kl<4;kl++){
                int kk = 4*wc + kl;
                uint32_t a[4] = { p[2*kl][0], p[2*kl][1], p[2*kl+1][0], p[2*kl+1][1] };
                #pragma unroll
                for (int ni2=0;ni2<4;ni2++){
                    uint32_t v0,v1,v2,v3;
                    ldsm4t(v0,v1,v2,v3, vb + (16*kk + t_k)*LDT + (16*ni2 + t_n)*2);
                    mmaf16(o[2*ni2],   a, v0, v1);
                    mmaf16(o[2*ni2+1], a, v2, v3);
                }
            }
        }
        // no end barrier: next iter's top barrier protects all buffers
    }

    // ---- epilogue: reduce l, pair-sum partial O (QD region reused), write ctx ----
    lrow0 += __shfl_xor_sync(0xffffffffu, lrow0, 1);
    lrow0 += __shfl_xor_sync(0xffffffffu, lrow0, 2);
    lrow1 += __shfl_xor_sync(0xffffffffu, lrow1, 1);
    lrow1 += __shfl_xor_sync(0xffffffffu, lrow1, 2);
    SX[i0*2 + wc]     = lrow0;
    SX[(i0+8)*2 + wc] = lrow1;
    barp(1 + r);                       // partner's last gather reads done

    float* OS = (float*)(sm + OQD);    // [128][66] floats fits in QD region
    if (wc == 0){
        #pragma unroll
        for (int ni=0; ni<8; ni++){
            int d = 8*ni + 2*tig;
            OS[i0*66 + d]       = o[ni][0];
            OS[i0*66 + d + 1]   = o[ni][1];
            OS[(i0+8)*66 + d]   = o[ni][2];
            OS[(i0+8)*66 + d+1] = o[ni][3];
        }
    }
    barp(1 + r);
    if (wc == 1){
        float lt0 = lrow0 + SX[i0*2 + 0];
        float lt1 = lrow1 + SX[(i0+8)*2 + 0];
        float inv0 = 1.f / lt0;
        float inv1 = 1.f / lt1;
        int bb = bh>>4, hh = bh&15;
        int s1r = l0 + i0;
        __half* base1 = g_ctx_h + ((size_t)(bb*SQ + s1r  ))*EM + hh*DH;
        __half* base2 = g_ctx_h + ((size_t)(bb*SQ + s1r+8))*EM + hh*DH;
        #pragma unroll
        for (int ni=0; ni<8; ni++){
            int d = 8*ni + 2*tig;
            float v0 = (o[ni][0] + OS[i0*66 + d])       * inv0;
            float v1 = (o[ni][1] + OS[i0*66 + d + 1])   * inv0;
            float v2 = (o[ni][2] + OS[(i0+8)*66 + d])   * inv1;
            float v3 = (o[ni][3] + OS[(i0+8)*66 + d+1]) * inv1;
            *(__half2*)&base1[d] = __floats2half2_rn(v0, v1);
            *(__half2*)&base2[d] = __floats2half2_rn(v2, v3);
        }
    }
}

// ---------------------------------------------------------------------------
// LayerNorm: 512 threads, 2 rows per block
// ---------------------------------------------------------------------------
__global__ __launch_bounds__(512) void ln_kernel(const float* __restrict__ gamma,
    const float* __restrict__ beta, float* __restrict__ out)
{
    int hf = threadIdx.x >> 8;           // 0/1: which row
    int tid = threadIdx.x & 255;
    int row = blockIdx.x*2 + hf;
    int w = tid>>5, lane = tid&31;
    const float4 x4 = ((const float4*)(g_h + (size_t)row*EM))[tid];
    float s = x4.x + x4.y + x4.z + x4.w;
    float q = x4.x*x4.x + x4.y*x4.y + x4.z*x4.z + x4.w*x4.w;
    #pragma unroll
    for (int off=16; off; off>>=1){
        s += __shfl_xor_sync(0xffffffffu, s, off);
        q += __shfl_xor_sync(0xffffffffu, q, off);
    }
    __shared__ float ss[2][8], qs[2][8];
    __shared__ float mean_s[2], rs_s[2];
    if (lane==0){ ss[hf][w]=s; qs[hf][w]=q; }
    __syncthreads();
    if (w==0){
        float s2 = (lane<8) ? ss[hf][lane] : 0.f;
        float q2 = (lane<8) ? qs[hf][lane] : 0.f;
        #pragma unroll
        for (int off=4; off; off>>=1){
            s2 += __shfl_xor_sync(0xffffffffu, s2, off);
            q2 += __shfl_xor_sync(0xffffffffu, q2, off);
        }
        if (lane==0){
            float mean = s2 * (1.f/1024.f);
            float var  = fmaxf(q2 * (1.f/1024.f) - mean*mean, 0.f);
            mean_s[hf] = mean;
            rs_s[hf]   = rsqrtf(var + 1e-12f);
        }
    }
    __syncthreads();
    float mean = mean_s[hf], rs = rs_s[hf];
    float4 gm = ((const float4*)gamma)[tid];
    float4 bt = ((const float4*)beta)[tid];
    float4 y;
    y.x = (x4.x - mean)*rs*gm.x + bt.x;
    y.y = (x4.y - mean)*rs*gm.y + bt.y;
    y.z = (x4.z - mean)*rs*gm.z + bt.z;
    y.w = (x4.w - mean)*rs*gm.w + bt.w;
    ((float4*)(out + (size_t)row*EM))[tid] = y;
}

// ---------------------------------------------------------------------------
extern "C" void kernel_launch(void* const* d_in, const int* in_sizes, int n_in,
                              void* d_out, int out_size)
{
    const float* hidden = (const float*)d_in[0];
    const float* Wq  = (const float*)d_in[1];
    const float* bq  = (const float*)d_in[2];
    const float* Wk  = (const float*)d_in[3];
    const float* bk  = (const float*)d_in[4];
    const float* Wv  = (const float*)d_in[5];
    const float* bv  = (const float*)d_in[6];
    const float* dist= (const float*)d_in[7];
    const float* Wo  = (const float*)d_in[8];
    const float* bo  = (const float*)d_in[9];
    const float* gam = (const float*)d_in[10];
    const float* bet = (const float*)d_in[11];
    float* out = (float*)d_out;

    cudaFuncSetAttribute(attn_h, cudaFuncAttributeMaxDynamicSharedMemorySize, ATTN_SMEM);
    cudaFuncSetAttribute(gemm_h, cudaFuncAttributeMaxDynamicSharedMemorySize, GSMEM);

    __half *hidh, *wt, *wot, *ctxh;
    float *biasq;
    cudaGetSymbolAddress((void**)&hidh,  g_hid_h);
    cudaGetSymbolAddress((void**)&wt,    g_wt);
    cudaGetSymbolAddress((void**)&wot,   g_wot);
    cudaGetSymbolAddress((void**)&ctxh,  g_ctx_h);
    cudaGetSymbolAddress((void**)&biasq, g_biasqkv);

    // launch order puts attn_h at index 3 (the launch ncu captures)
    pack_h_kernel<<<NTOK*EM/4/256, 256>>>(hidden, hidh, NTOK*EM/4);          // 0
    pack_wt_all<<<dim3(32,32,5), 256>>>(Wq, Wk, Wv, Wo, dist, bq, bk, bv);   // 1
    gemm_h<<<dim3(64,24), 256, GSMEM>>>(hidh, wt, biasq, nullptr, 0);        // 2
    attn_h<<<dim3(128,8), 512, ATTN_SMEM>>>();                               // 3 <- ncu
    gemm_h<<<dim3(64,8), 256, GSMEM>>>(ctxh, wot, bo, hidden, 1);            // 4
    ln_kernel<<<NTOK/2, 512>>>(gam, bet, out);                               // 5
}

// round 16
// speedup vs baseline: 1.5678x; 1.0019x over previous
#include <cuda_runtime.h>
#include <cuda_fp16.h>
#include <cstdint>

#define HN 16
#define DH 64
#define EM 1024
#define SQ 1024
#define BA 8
#define BH (BA*HN)
#define NTOK (BA*SQ)

// Scratch (device globals; allocation-free per harness rules)
__device__ __half g_hid_h[NTOK*EM];
__device__ __half g_wt[3*EM*EM];      // [3072 n][1024 k] (W^T, fp16)
__device__ __half g_wot[EM*EM];       // [1024 n][1024 k]
__device__ __half g_qh[BH*SQ*DH];
__device__ __half g_kh[BH*SQ*DH];
__device__ __half g_vh[BH*SQ*DH];
__device__ __half g_ctx_h[NTOK*EM];
__device__ __half g_dist_h[2047*DH];  // pre-scaled by C2F
__device__ float  g_biasqkv[3*EM];
__device__ float  g_h[NTOK*EM];

// ---------------------------------------------------------------------------
// PTX helpers (all non-'a' features: sm_80-class, compile at sm_103)
// ---------------------------------------------------------------------------
__device__ __forceinline__ uint32_t s2u(const void* p){
    uint32_t a; asm("{ .reg .u64 t; cvta.to.shared.u64 t, %1; cvt.u32.u64 %0, t; }" : "=r"(a) : "l"(p)); return a;
}
__device__ __forceinline__ void ldsm4(uint32_t& r0, uint32_t& r1, uint32_t& r2, uint32_t& r3, uint32_t addr){
    asm volatile("ldmatrix.sync.aligned.m8n8.x4.shared.b16 {%0,%1,%2,%3}, [%4];"
        : "=r"(r0), "=r"(r1), "=r"(r2), "=r"(r3) : "r"(addr));
}
__device__ __forceinline__ void ldsm4t(uint32_t& r0, uint32_t& r1, uint32_t& r2, uint32_t& r3, uint32_t addr){
    asm volatile("ldmatrix.sync.aligned.m8n8.x4.trans.shared.b16 {%0,%1,%2,%3}, [%4];"
        : "=r"(r0), "=r"(r1), "=r"(r2), "=r"(r3) : "r"(addr));
}
__device__ __forceinline__ void mmaf16(float c[4], const uint32_t a[4], uint32_t b0, uint32_t b1){
    asm volatile("mma.sync.aligned.m16n8k16.row.col.f32.f16.f16.f32 "
        "{%0,%1,%2,%3}, {%4,%5,%6,%7}, {%8,%9}, {%0,%1,%2,%3};"
        : "+f"(c[0]), "+f"(c[1]), "+f"(c[2]), "+f"(c[3])
        : "r"(a[0]), "r"(a[1]), "r"(a[2]), "r"(a[3]), "r"(b0), "r"(b1));
}
__device__ __forceinline__ void cp16(uint32_t dst, const void* src){
    asm volatile("cp.async.ca.shared.global [%0], [%1], 16;" :: "r"(dst), "l"(src));
}
__device__ __forceinline__ void cp16cg(uint32_t dst, const void* src){
    asm volatile("cp.async.cg.shared.global [%0], [%1], 16;" :: "r"(dst), "l"(src));
}
__device__ __forceinline__ void cp_commit(){ asm volatile("cp.async.commit_group;" ::: "memory"); }
template<int N> __device__ __forceinline__ void cp_wait(){
    asm volatile("cp.async.wait_group %0;" :: "n"(N) : "memory");
}
__device__ __forceinline__ float ex2(float x){
    float y; asm("ex2.approx.f32 %0, %1;" : "=f"(y) : "f"(x)); return y;
}
__device__ __forceinline__ void barp(int id){
    asm volatile("bar.sync %0, 64;" :: "r"(id) : "memory");
}

#define C2F 0.18033688f         // 0.125 * log2(e)

// ---------------------------------------------------------------------------
// Unified pack kernel (single launch):
//   z 0..3 : weight transposes Wq,Wk,Wv,Wo  (fp32 [k][n] -> fp16 [n][k])
//   z 4    : dist fp16 pack (pre-scaled by C2F) + bias copy
//   z 5..12: hidden fp32 -> fp16 (8 planes x 1024 blocks)
// ---------------------------------------------------------------------------
__global__ __launch_bounds__(256) void pack_all(const float* __restrict__ Wq,
    const float* __restrict__ Wk, const float* __restrict__ Wv,
    const float* __restrict__ Wo, const float* __restrict__ dist,
    const float* __restrict__ bq, const float* __restrict__ bk,
    const float* __restrict__ bv, const float* __restrict__ hidden)
{
    int z = blockIdx.z;
    if (z >= 5){
        int bid = (z-5)*1024 + blockIdx.y*32 + blockIdx.x;
        int i = bid*256 + threadIdx.x;            // < NTOK*EM/4 = 2097152 exactly
        float4 v = ((const float4*)hidden)[i];
        __half2* d = (__half2*)g_hid_h + i*2;
        d[0] = __floats2half2_rn(v.x, v.y);
        d[1] = __floats2half2_rn(v.z, v.w);
        return;
    }
    if (z == 4){
        int bid = blockIdx.y*32 + blockIdx.x;
        int i = bid*256 + threadIdx.x;
        const int ND4 = 2047*DH/4;                // 32752 float4 of dist
        if (i < ND4){
            float4 v = ((const float4*)dist)[i];
            __half2* d = (__half2*)g_dist_h + i*2;
            d[0] = __floats2half2_rn(v.x*C2F, v.y*C2F);
            d[1] = __floats2half2_rn(v.z*C2F, v.w*C2F);
        } else {
            int j = i - ND4;
            if (j < 3*EM){
                int b = j >> 10, e = j & 1023;
                const float* s = (b==0) ? bq : (b==1 ? bk : bv);
                g_biasqkv[j] = s[e];
            }
        }
        return;
    }
    __shared__ float t[32][33];
    const float* W = (z==0)?Wq:(z==1)?Wk:(z==2)?Wv:Wo;
    __half* Wt = (z<3) ? (g_wt + (size_t)z*EM*EM) : g_wot;
    int bn = blockIdx.x*32, bk2 = blockIdx.y*32;
    int tx = threadIdx.x & 31, ty = threadIdx.x >> 5;
    #pragma unroll
    for (int i=0;i<32;i+=8)
        t[ty+i][tx] = W[(size_t)(bk2+ty+i)*EM + bn+tx];
    __syncthreads();
    #pragma unroll
    for (int i=0;i<32;i+=8)
        Wt[(size_t)(bn+ty+i)*EM + bk2+tx] = __float2half_rn(t[tx][ty+i]);
}

// ---------------------------------------------------------------------------
// fp16 GEMM: C[128 x 128] tile, K=1024 in 16 chunks of 64, 3-stage cp.async
// pipeline (stage rows 144B, conflict-free), ldmatrix + mma16816.
// ---------------------------------------------------------------------------
#define GLD2 144               // bytes per 64-half row (128 data + 16 pad)
#define GSTG2 (128*GLD2)       // 18432 B per matrix per stage
#define GSMEM (3*2*GSTG2)      // 110592

__global__ __launch_bounds__(256,2) void gemm_h(const __half* __restrict__ A,
    const __half* __restrict__ Bt, const float* __restrict__ bias,
    const float* __restrict__ resid, int mode)
{
    extern __shared__ char sm[];
    uint32_t sb = s2u(sm);
    int tid = threadIdx.x, w = tid>>5, lane = tid&31;
    int g = lane>>2, tig = lane&3;
    int rows0 = (w>>2)*64, cols0 = (w&3)*32;
    int m0 = blockIdx.x*128, n0 = blockIdx.y*128;

    float c[4][4][4];
    #pragma unroll
    for (int i=0;i<4;i++)
        #pragma unroll
        for (int j=0;j<4;j++){ c[i][j][0]=0.f; c[i][j][1]=0.f; c[i][j][2]=0.f; c[i][j][3]=0.f; }

    auto load_st = [&](int st, int kc){      // kc in units of 64
        uint32_t base = sb + st*2*GSTG2;
        const __half* gA = A + (size_t)m0*EM + kc*64;
        const __half* gB = Bt + (size_t)n0*EM + kc*64;
        #pragma unroll
        for (int i=0;i<4;i++){
            int cix = tid + 256*i;
            int row = cix>>3, part = cix&7;
            cp16(base + row*GLD2 + part*16, gA + (size_t)row*EM + part*8);
        }
        #pragma unroll
        for (int i=0;i<4;i++){
            int cix = tid + 256*i;
            int row = cix>>3, part = cix&7;
            cp16(base + GSTG2 + row*GLD2 + part*16, gB + (size_t)row*EM + part*8);
        }
    };

    load_st(0, 0); cp_commit();
    load_st(1, 1); cp_commit();

    int a_r = lane & 15;
    int a_k = (lane>>4)<<3;
    int b_n = (lane&7) + ((lane>=16)?8:0);
    int b_k = (lane&8)?8:0;

    for (int kc=0; kc<16; kc++){
        if (kc+2 < 16) load_st((kc+2)%3, kc+2);
        cp_commit();
        cp_wait<2>();
        __syncthreads();
        uint32_t Ab = sb + (kc%3)*2*GSTG2;
        uint32_t Bb = Ab + GSTG2;
        #pragma unroll
        for (int ks=0; ks<4; ks++){
            uint32_t a[4][4];
            #pragma unroll
            for (int mi=0;mi<4;mi++)
                ldsm4(a[mi][0],a[mi][1],a[mi][2],a[mi][3],
                      Ab + (rows0+16*mi+a_r)*GLD2 + (ks*16 + a_k)*2);
            #pragma unroll
            for (int ni2=0;ni2<2;ni2++){
                uint32_t b0,b1,b2,b3;
                ldsm4(b0,b1,b2,b3, Bb + (cols0+16*ni2+b_n)*GLD2 + (ks*16 + b_k)*2);
                #pragma unroll
                for (int mi=0;mi<4;mi++){
                    mmaf16(c[mi][2*ni2],   a[mi], b0, b1);
                    mmaf16(c[mi][2*ni2+1], a[mi], b2, b3);
                }
            }
        }
        __syncthreads();
    }

    #pragma unroll
    for (int mi=0; mi<4; mi++){
        int rowA = rows0 + 16*mi + g;
        int t1 = m0 + rowA, t2 = t1 + 8;
        #pragma unroll
        for (int ni=0; ni<4; ni++){
            int col = cols0 + 8*ni + 2*tig;
            int nglob = n0 + col;
            float bv0 = bias[nglob], bv1 = bias[nglob+1];
            if (mode == 0){
                int mat = nglob>>10, e = nglob&1023, h = e>>6, d = e&63;
                __half* outp = (mat==0) ? g_qh : (mat==1 ? g_kh : g_vh);
                int bb1 = t1>>10, s1 = t1&1023;
                int bb2 = t2>>10, s2 = t2&1023;
                *(__half2*)&outp[(((size_t)(bb1*HN+h))*SQ + s1)*DH + d] =
                    __floats2half2_rn(c[mi][ni][0]+bv0, c[mi][ni][1]+bv1);
                *(__half2*)&outp[(((size_t)(bb2*HN+h))*SQ + s2)*DH + d] =
                    __floats2half2_rn(c[mi][ni][2]+bv0, c[mi][ni][3]+bv1);
            } else {
                const float* r1 = &resid[(size_t)t1*EM + nglob];
                const float* r2 = &resid[(size_t)t2*EM + nglob];
                float2 v1; v1.x = c[mi][ni][0]+bv0+r1[0]; v1.y = c[mi][ni][1]+bv1+r1[1];
                float2 v2; v2.x = c[mi][ni][2]+bv0+r2[0]; v2.y = c[mi][ni][3]+bv1+r2[1];
                *(float2*)&g_h[(size_t)t1*EM + nglob] = v1;
                *(float2*)&g_h[(size_t)t2*EM + nglob] = v2;
            }
        }
    }
}

// ---------------------------------------------------------------------------
// Flash attention, 512 threads, warp pairs, max-free softmax, double-buffered
// K/V, compact QD/KD, D ring. (unchanged champion)
// ---------------------------------------------------------------------------
#define LDT 144                 // bytes per 64-half row (128 data + 16 pad)
#define LQD 368                 // bytes per compact QD/KD row (184 halves)
#define OQ  0
#define OKA 18432
#define OKB 36864
#define OVA 55296
#define OVB 73728
#define OD  92160               // 256-row ring x 144B
#define OQD 129024              // 128 x LQD   (u = t - 16r)
#define OKD 176128              // 128 x LQD   (v = t - 112 + 16r)
#define OSX 223232
#define ATTN_SMEM 225280

__global__ __launch_bounds__(512,1) void attn_h()
{
    extern __shared__ char sm[];
    uint32_t sb = s2u(sm);

    int bh = blockIdx.x;
    int l0 = blockIdx.y*128;
    int tid = threadIdx.x;
    int w = tid>>5, lane = tid&31, g = lane>>2, tig = lane&3;
    int r = w>>1, wc = w&1;

    int a_r = lane & 15;
    int a_k = (lane>>4)<<3;
    int b_n = (lane&7) + ((lane>=16)?8:0);
    int b_k = (lane&8)?8:0;
    int t_k = (lane&7) + ((lane&8)?8:0);
    int t_n = (lane>=16)?8:0;
    int i0 = 16*r + g;

    // zero logical dist row 255 for rt=0
    if (tid < 9) *(uint4*)(sm + OD + 255*LDT + tid*16) = make_uint4(0,0,0,0);

    // prologue: group A = Q + K0->KA + V0->VA ; group B = D0 (255 rows)
    {
        const __half* qg = g_qh + ((size_t)bh*SQ + l0)*DH;
        const __half* kg = g_kh + ((size_t)bh*SQ)*DH;
        const __half* vg = g_vh + ((size_t)bh*SQ)*DH;
        #pragma unroll
        for (int i=0;i<2;i++){
            int cix = tid + 512*i;
            int row = cix>>3, part = cix&7;
            cp16cg(sb + OQ  + row*LDT + part*16, qg + (size_t)row*DH + part*8);
            cp16cg(sb + OKA + row*LDT + part*16, kg + (size_t)row*DH + part*8);
            cp16cg(sb + OVA + row*LDT + part*16, vg + (size_t)row*DH + part*8);
        }
        cp_commit();
        const __half* dg = g_dist_h + (size_t)(l0 + 896)*DH;
        #pragma unroll
        for (int i=0;i<4;i++){
            int cix = tid + 512*i;
            if (cix < 255*8){
                int row = cix>>3, part = cix&7;
                cp16cg(sb + OD + row*LDT + part*16, dg + (size_t)row*DH + part*8);
            }
        }
        cp_commit();
    }

    float o[8][4];
    #pragma unroll
    for (int i=0;i<8;i++){ o[i][0]=0.f; o[i][1]=0.f; o[i][2]=0.f; o[i][3]=0.f; }
    float lrow0 = 0.f, lrow1 = 0.f;

    uint32_t qa[4][4];
    float* SX = (float*)(sm + OSX);

    for (int rt=0; rt<8; rt++){
        cp_wait<0>();
        __syncthreads();               // K, V (top group) + D (mid group) for rt ready

        uint32_t kb = sb + ((rt&1) ? OKB : OKA);
        uint32_t vb = sb + ((rt&1) ? OVB : OVA);

        if (rt == 0){
            #pragma unroll
            for (int ks=0;ks<4;ks++)
                ldsm4(qa[ks][0],qa[ks][1],qa[ks][2],qa[ks][3],
                      sb + OQ + (16*r+a_r)*LDT + (ks*16 + a_k)*2);
        }
        if (rt < 7){                   // prefetch K,V for rt+1 into the other buffers
            uint32_t kn = sb + ((rt&1) ? OKA : OKB);
            uint32_t vn = sb + ((rt&1) ? OVA : OVB);
            const __half* kg = g_kh + ((size_t)bh*SQ + (rt+1)*128)*DH;
            const __half* vg = g_vh + ((size_t)bh*SQ + (rt+1)*128)*DH;
            #pragma unroll
            for (int i=0;i<2;i++){
                int cix = tid + 512*i;
                int row = cix>>3, part = cix&7;
                cp16cg(kn + row*LDT + part*16, kg + (size_t)row*DH + part*8);
                cp16cg(vn + row*LDT + part*16, vg + (size_t)row*DH + part*8);
            }
            cp_commit();
        }

        int rowoff = (rt & 1) << 7;    // D ring offset

        // ---- QD tiles (pair covers [r..r+8]); store at [i][t-16r] ----
        {
            int T0 = wc ? r : (r+5);
            int nT = wc ? 5 : 4;
            for (int ti=0; ti<nT; ti++){
                int t0r = (T0+ti)<<4;
                int u0 = t0r - 16*r;
                uint32_t dbase = sb + OD + (((t0r + b_n) + rowoff) & 255)*LDT;
                float qd[2][4];
                qd[0][0]=0.f;qd[0][1]=0.f;qd[0][2]=0.f;qd[0][3]=0.f;
                qd[1][0]=0.f;qd[1][1]=0.f;qd[1][2]=0.f;qd[1][3]=0.f;
                #pragma unroll
                for (int ks=0;ks<4;ks++){
                    uint32_t b0,b1,b2,b3;
                    ldsm4(b0,b1,b2,b3, dbase + (ks*16 + b_k)*2);
                    mmaf16(qd[0], qa[ks], b0, b1);
                    mmaf16(qd[1], qa[ks], b2, b3);
                }
                #pragma unroll
                for (int f=0;f<2;f++){
                    int u = u0 + 8*f + 2*tig;
                    *(__half2*)(sm + OQD + (size_t)i0*LQD + u*2)     = __floats2half2_rn(qd[f][0], qd[f][1]);
                    *(__half2*)(sm + OQD + (size_t)(i0+8)*LQD + u*2) = __floats2half2_rn(qd[f][2], qd[f][3]);
                }
            }
        }

        // ---- ka fragments (feed only KD) ----
        uint32_t ka[4][4];
        #pragma unroll
        for (int ks=0;ks<4;ks++)
            ldsm4(ka[ks][0],ka[ks][1],ka[ks][2],ka[ks][3],
                  kb + (16*r+a_r)*LDT + (ks*16 + a_k)*2);

        // ---- KD tiles (pair covers [7-r..15-r]); store at [j][t-112+16r] ----
        {
            int T0 = wc ? (7-r) : (12-r);
            int nT = wc ? 5 : 4;
            for (int ti=0; ti<nT; ti++){
                int t0r = (T0+ti)<<4;
                int v0 = t0r - 112 + 16*r;
                uint32_t dbase = sb + OD + (((t0r + b_n) + rowoff) & 255)*LDT;
                float kd[2][4];
                kd[0][0]=0.f;kd[0][1]=0.f;kd[0][2]=0.f;kd[0][3]=0.f;
                kd[1][0]=0.f;kd[1][1]=0.f;kd[1][2]=0.f;kd[1][3]=0.f;
                #pragma unroll
                for (int ks=0;ks<4;ks++){
                    uint32_t b0,b1,b2,b3;
                    ldsm4(b0,b1,b2,b3, dbase + (ks*16 + b_k)*2);
                    mmaf16(kd[0], ka[ks], b0, b1);
                    mmaf16(kd[1], ka[ks], b2, b3);
                }
                #pragma unroll
                for (int f=0;f<2;f++){
                    int v = v0 + 8*f + 2*tig;
                    *(__half2*)(sm + OKD + (size_t)i0*LQD + v*2)     = __floats2half2_rn(kd[f][0], kd[f][1]);
                    *(__half2*)(sm + OKD + (size_t)(i0+8)*LQD + v*2) = __floats2half2_rn(kd[f][2], kd[f][3]);
                }
            }
        }

        // ---- S = Q @ K^T (warp tile 16 x 64: cols [64wc, 64wc+64)) ----
        float cs[8][4];
        #pragma unroll
        for (int f=0;f<8;f++){ cs[f][0]=0.f; cs[f][1]=0.f; cs[f][2]=0.f; cs[f][3]=0.f; }
        #pragma unroll
        for (int ks=0;ks<4;ks++){
            #pragma unroll
            for (int ntl=0;ntl<4;ntl++){
                uint32_t b0,b1,b2,b3;
                ldsm4(b0,b1,b2,b3, kb + (16*(4*wc+ntl)+b_n)*LDT + (ks*16 + b_k)*2);
                mmaf16(cs[2*ntl],   qa[ks], b0, b1);
                mmaf16(cs[2*ntl+1], qa[ks], b2, b3);
            }
        }

        __syncthreads();               // QD/KD STS visible; D ring reads done

        if (rt < 7){                   // prefetch D(rt+1) into free ring half
            int poff = ((rt+1) & 1) << 7;
            const __half* dg = g_dist_h + (size_t)(l0 - (rt+1)*128 + 896)*DH;
            #pragma unroll
            for (int i=0;i<2;i++){
                int cix = tid + 512*i;
                int row = cix>>3, part = cix&7;
                cp16cg(sb + OD + (row + poff)*LDT + part*16, dg + (size_t)row*DH + part*8);
            }
            cp_commit();
        }

        // ---- max-free softmax: gather from compact layouts, exp2, pack ----
        {
            const char* QDb = sm + OQD;
            const char* KDb = sm + OKD;
            uint32_t p[8][2];
            #pragma unroll
            for (int f=0;f<8;f++){
                int j = 64*wc + 8*f + 2*tig;
                int uq = g + 127 - j;              // QD col for (i0, j)
                int jl = (8*f + 2*tig) & 15;
                int v00 = i0 + 15 - jl;            // KD col for (row j, i0)
                float b00 = __half2float(*(const __half*)(QDb + (size_t)i0*LQD + uq*2))
                          + __half2float(*(const __half*)(KDb + (size_t)j*LQD + v00*2));
                float b01 = __half2float(*(const __half*)(QDb + (size_t)i0*LQD + (uq-1)*2))
                          + __half2float(*(const __half*)(KDb + (size_t)(j+1)*LQD + (v00-1)*2));
                float b10 = __half2float(*(const __half*)(QDb + (size_t)(i0+8)*LQD + (uq+8)*2))
                          + __half2float(*(const __half*)(KDb + (size_t)j*LQD + (v00+8)*2));
                float b11 = __half2float(*(const __half*)(QDb + (size_t)(i0+8)*LQD + (uq+7)*2))
                          + __half2float(*(const __half*)(KDb + (size_t)(j+1)*LQD + (v00+7)*2));
                float p00 = ex2(fmaf(cs[f][0], C2F, b00));
                float p01 = ex2(fmaf(cs[f][1], C2F, b01));
                float p10 = ex2(fmaf(cs[f][2], C2F, b10));
                float p11 = ex2(fmaf(cs[f][3], C2F, b11));
                lrow0 += p00 + p01; lrow1 += p10 + p11;
                __half2 hA = __floats2half2_rn(p00, p01); p[f][0] = *(uint32_t*)&hA;
                __half2 hB = __floats2half2_rn(p10, p11); p[f][1] = *(uint32_t*)&hB;
            }

            // ---- O += P @ V over this warp's 64-key slice ----
            #pragma unroll
            for (int kl=0;kl<4;kl++){
                int kk = 4*wc + kl;
                uint32_t a[4] = { p[2*kl][0], p[2*kl][1], p[2*kl+1][0], p[2*kl+1][1] };
                #pragma unroll
                for (int ni2=0;ni2<4;ni2++){
                    uint32_t v0,v1,v2,v3;
                    ldsm4t(v0,v1,v2,v3, vb + (16*kk + t_k)*LDT + (16*ni2 + t_n)*2);
                    mmaf16(o[2*ni2],   a, v0, v1);
                    mmaf16(o[2*ni2+1], a, v2, v3);
                }
            }
        }
        // no end barrier: next iter's top barrier protects all buffers
    }

    // ---- epilogue: reduce l, pair-sum partial O (QD region reused), write ctx ----
    lrow0 += __shfl_xor_sync(0xffffffffu, lrow0, 1);
    lrow0 += __shfl_xor_sync(0xffffffffu, lrow0, 2);
    lrow1 += __shfl_xor_sync(0xffffffffu, lrow1, 1);
    lrow1 += __shfl_xor_sync(0xffffffffu, lrow1, 2);
    SX[i0*2 + wc]     = lrow0;
    SX[(i0+8)*2 + wc] = lrow1;
    barp(1 + r);                       // partner's last gather reads done

    float* OS = (float*)(sm + OQD);    // [128][66] floats fits in QD region
    if (wc == 0){
        #pragma unroll
        for (int ni=0; ni<8; ni++){
            int d = 8*ni + 2*tig;
            OS[i0*66 + d]       = o[ni][0];
            OS[i0*66 + d + 1]   = o[ni][1];
            OS[(i0+8)*66 + d]   = o[ni][2];
            OS[(i0+8)*66 + d+1] = o[ni][3];
        }
    }
    barp(1 + r);
    if (wc == 1){
        float lt0 = lrow0 + SX[i0*2 + 0];
        float lt1 = lrow1 + SX[(i0+8)*2 + 0];
        float inv0 = 1.f / lt0;
        float inv1 = 1.f / lt1;
        int bb = bh>>4, hh = bh&15;
        int s1r = l0 + i0;
        __half* base1 = g_ctx_h + ((size_t)(bb*SQ + s1r  ))*EM + hh*DH;
        __half* base2 = g_ctx_h + ((size_t)(bb*SQ + s1r+8))*EM + hh*DH;
        #pragma unroll
        for (int ni=0; ni<8; ni++){
            int d = 8*ni + 2*tig;
            float v0 = (o[ni][0] + OS[i0*66 + d])       * inv0;
            float v1 = (o[ni][1] + OS[i0*66 + d + 1])   * inv0;
            float v2 = (o[ni][2] + OS[(i0+8)*66 + d])   * inv1;
            float v3 = (o[ni][3] + OS[(i0+8)*66 + d+1]) * inv1;
            *(__half2*)&base1[d] = __floats2half2_rn(v0, v1);
            *(__half2*)&base2[d] = __floats2half2_rn(v2, v3);
        }
    }
}

// ---------------------------------------------------------------------------
// LayerNorm: 512 threads, 2 rows per block
// ---------------------------------------------------------------------------
__global__ __launch_bounds__(512) void ln_kernel(const float* __restrict__ gamma,
    const float* __restrict__ beta, float* __restrict__ out)
{
    int hf = threadIdx.x >> 8;           // 0/1: which row
    int tid = threadIdx.x & 255;
    int row = blockIdx.x*2 + hf;
    int w = tid>>5, lane = tid&31;
    const float4 x4 = ((const float4*)(g_h + (size_t)row*EM))[tid];
    float s = x4.x + x4.y + x4.z + x4.w;
    float q = x4.x*x4.x + x4.y*x4.y + x4.z*x4.z + x4.w*x4.w;
    #pragma unroll
    for (int off=16; off; off>>=1){
        s += __shfl_xor_sync(0xffffffffu, s, off);
        q += __shfl_xor_sync(0xffffffffu, q, off);
    }
    __shared__ float ss[2][8], qs[2][8];
    __shared__ float mean_s[2], rs_s[2];
    if (lane==0){ ss[hf][w]=s; qs[hf][w]=q; }
    __syncthreads();
    if (w==0){
        float s2 = (lane<8) ? ss[hf][lane] : 0.f;
        float q2 = (lane<8) ? qs[hf][lane] : 0.f;
        #pragma unroll
        for (int off=4; off; off>>=1){
            s2 += __shfl_xor_sync(0xffffffffu, s2, off);
            q2 += __shfl_xor_sync(0xffffffffu, q2, off);
        }
        if (lane==0){
            float mean = s2 * (1.f/1024.f);
            float var  = fmaxf(q2 * (1.f/1024.f) - mean*mean, 0.f);
            mean_s[hf] = mean;
            rs_s[hf]   = rsqrtf(var + 1e-12f);
        }
    }
    __syncthreads();
    float mean = mean_s[hf], rs = rs_s[hf];
    float4 gm = ((const float4*)gamma)[tid];
    float4 bt = ((const float4*)beta)[tid];
    float4 y;
    y.x = (x4.x - mean)*rs*gm.x + bt.x;
    y.y = (x4.y - mean)*rs*gm.y + bt.y;
    y.z = (x4.z - mean)*rs*gm.z + bt.z;
    y.w = (x4.w - mean)*rs*gm.w + bt.w;
    ((float4*)(out + (size_t)row*EM))[tid] = y;
}

// ---------------------------------------------------------------------------
extern "C" void kernel_launch(void* const* d_in, const int* in_sizes, int n_in,
                              void* d_out, int out_size)
{
    const float* hidden = (const float*)d_in[0];
    const float* Wq  = (const float*)d_in[1];
    const float* bq  = (const float*)d_in[2];
    const float* Wk  = (const float*)d_in[3];
    const float* bk  = (const float*)d_in[4];
    const float* Wv  = (const float*)d_in[5];
    const float* bv  = (const float*)d_in[6];
    const float* dist= (const float*)d_in[7];
    const float* Wo  = (const float*)d_in[8];
    const float* bo  = (const float*)d_in[9];
    const float* gam = (const float*)d_in[10];
    const float* bet = (const float*)d_in[11];
    float* out = (float*)d_out;

    cudaFuncSetAttribute(attn_h, cudaFuncAttributeMaxDynamicSharedMemorySize, ATTN_SMEM);
    cudaFuncSetAttribute(gemm_h, cudaFuncAttributeMaxDynamicSharedMemorySize, GSMEM);

    __half *hidh, *wt, *wot, *ctxh;
    float *biasq;
    cudaGetSymbolAddress((void**)&hidh,  g_hid_h);
    cudaGetSymbolAddress((void**)&wt,    g_wt);
    cudaGetSymbolAddress((void**)&wot,   g_wot);
    cudaGetSymbolAddress((void**)&ctxh,  g_ctx_h);
    cudaGetSymbolAddress((void**)&biasq, g_biasqkv);

    pack_all<<<dim3(32,32,13), 256>>>(Wq, Wk, Wv, Wo, dist, bq, bk, bv, hidden); // 0
    gemm_h<<<dim3(64,24), 256, GSMEM>>>(hidh, wt, biasq, nullptr, 0);            // 1
    attn_h<<<dim3(128,8), 512, ATTN_SMEM>>>();                                   // 2
    gemm_h<<<dim3(64,8), 256, GSMEM>>>(ctxh, wot, bo, hidden, 1);                // 3 <- ncu
    ln_kernel<<<NTOK/2, 512>>>(gam, bet, out);                                   // 4
}